// round 5
// baseline (speedup 1.0000x reference)
#include <cuda_runtime.h>
#include <cuda_fp16.h>
#include <math.h>
#include <stdint.h>

#define NN 50000
#define EE 800000
#define IN_DIM 128
#define HID 128
#define OUT_DIM 40
#define KHOP 10
#define AH 64
#define ALPHA 0.1f
#define EPS 1e-5f

#define SCAN_B 256
#define SCAN_NB ((NN + SCAN_B - 1) / SCAN_B)   // 196

// ----------------------------------------------------------------------------
// Static device scratch
// ----------------------------------------------------------------------------
__device__ __half g_xsh[(KHOP + 1) * (size_t)NN * HID];  // 140.8 MB: h at every hop (fp16)
__device__ float  g_h1[(size_t)NN * HID];                // stem layer-1 output (fp32)
__device__ float  g_wsum[NN];
__device__ int    g_deg[NN];
__device__ int    g_rowptr[NN + 1];
__device__ int    g_cursor[NN];
__device__ int    g_bsum[SCAN_NB];
__device__ int    g_boff[SCAN_NB];
__device__ float2 g_edge[EE];                            // {src bits, enorm} CSR by dest

// transposed weights + folded BN constants
__device__ float g_Wt1[IN_DIM * HID];    // [k][n]
__device__ float g_Wt2[HID * HID];       // [k][n]
__device__ float g_attWt1[2 * HID * AH]; // [c][o]
__device__ float g_h1Wt[HID * (HID / 2)];// [c][o]  128x64
__device__ float g_h2Wt[(HID / 2) * OUT_DIM]; // [c][o] 64x40
__device__ float g_A1[HID], g_C1[HID], g_A2[HID], g_C2[HID], g_A3[HID / 2], g_C3[HID / 2];

// 4 halves <-> 4 floats helpers
__device__ __forceinline__ float4 h4_to_f4(uint2 raw) {
    __half2 a = *(__half2*)&raw.x;
    __half2 b = *(__half2*)&raw.y;
    float2 fa = __half22float2(a);
    float2 fb = __half22float2(b);
    return make_float4(fa.x, fa.y, fb.x, fb.y);
}
__device__ __forceinline__ uint2 f4_to_h4(float4 v) {
    __half2 a = __floats2half2_rn(v.x, v.y);
    __half2 b = __floats2half2_rn(v.z, v.w);
    uint2 r;
    r.x = *(unsigned*)&a;
    r.y = *(unsigned*)&b;
    return r;
}

// ----------------------------------------------------------------------------
// Prep
// ----------------------------------------------------------------------------
__global__ void zero_kernel() {
    int i = blockIdx.x * blockDim.x + threadIdx.x;
    if (i < NN) { g_wsum[i] = 0.f; g_deg[i] = 0; g_cursor[i] = 0; }
}

__global__ void prep_kernel(const float* __restrict__ lin1_w, const float* __restrict__ lin1_b,
                            const float* __restrict__ bn1_g, const float* __restrict__ bn1_b,
                            const float* __restrict__ bn1_m, const float* __restrict__ bn1_v,
                            const float* __restrict__ lin2_w, const float* __restrict__ lin2_b,
                            const float* __restrict__ bn2_g, const float* __restrict__ bn2_b,
                            const float* __restrict__ bn2_m, const float* __restrict__ bn2_v,
                            const float* __restrict__ att1_w,
                            const float* __restrict__ head1_w, const float* __restrict__ head1_b,
                            const float* __restrict__ bn3_g, const float* __restrict__ bn3_b,
                            const float* __restrict__ bn3_m, const float* __restrict__ bn3_v,
                            const float* __restrict__ head2_w) {
    int tid = blockIdx.x * blockDim.x + threadIdx.x;
    if (tid < IN_DIM * HID) {
        int k = tid >> 7, n = tid & 127;
        g_Wt1[tid] = lin1_w[n * IN_DIM + k];
        g_Wt2[tid] = lin2_w[n * HID + k];
    }
    if (tid < 2 * HID * AH) {
        int c = tid >> 6, o = tid & 63;
        g_attWt1[tid] = att1_w[o * (2 * HID) + c];
    }
    if (tid < HID * (HID / 2)) {
        int c = tid >> 6, o = tid & 63;
        g_h1Wt[tid] = head1_w[o * HID + c];
    }
    if (tid < (HID / 2) * OUT_DIM) {
        int c = tid / OUT_DIM, o = tid % OUT_DIM;
        g_h2Wt[tid] = head2_w[o * (HID / 2) + c];
    }
    if (tid < HID) {
        float a1 = bn1_g[tid] * rsqrtf(bn1_v[tid] + EPS);
        g_A1[tid] = a1;
        g_C1[tid] = lin1_b[tid] * a1 + bn1_b[tid] - bn1_m[tid] * a1;
        float a2 = bn2_g[tid] * rsqrtf(bn2_v[tid] + EPS);
        g_A2[tid] = a2;
        g_C2[tid] = lin2_b[tid] * a2 + bn2_b[tid] - bn2_m[tid] * a2;
    }
    if (tid < HID / 2) {
        float a3 = bn3_g[tid] * rsqrtf(bn3_v[tid] + EPS);
        g_A3[tid] = a3;
        g_C3[tid] = head1_b[tid] * a3 + bn3_b[tid] - bn3_m[tid] * a3;
    }
}

// ----------------------------------------------------------------------------
// Graph preprocessing
// ----------------------------------------------------------------------------
__global__ void count_kernel(const int* __restrict__ ei, const float* __restrict__ ew) {
    int e = blockIdx.x * blockDim.x + threadIdx.x;
    if (e >= EE) return;
    int row = ei[e];
    int col = ei[EE + e];
    atomicAdd(&g_wsum[row], ew[e]);
    atomicAdd(&g_deg[col], 1);
}

__global__ void scanA_kernel() {
    __shared__ int sh[SCAN_B];
    int t = threadIdx.x;
    int i = blockIdx.x * SCAN_B + t;
    int v = (i < NN) ? g_deg[i] : 0;
    sh[t] = v;
    __syncthreads();
#pragma unroll
    for (int off = SCAN_B / 2; off > 0; off >>= 1) {
        if (t < off) sh[t] += sh[t + off];
        __syncthreads();
    }
    if (t == 0) g_bsum[blockIdx.x] = sh[0];
}

__global__ void scanB_kernel() {
    __shared__ int sh[SCAN_NB];
    int t = threadIdx.x;
    int v = (t < SCAN_NB) ? g_bsum[t] : 0;
    if (t < SCAN_NB) sh[t] = v;
    __syncthreads();
    for (int off = 1; off < SCAN_NB; off <<= 1) {
        int x = (t < SCAN_NB && t >= off) ? sh[t - off] : 0;
        __syncthreads();
        if (t < SCAN_NB) sh[t] += x;
        __syncthreads();
    }
    if (t < SCAN_NB) g_boff[t] = sh[t] - v;  // exclusive
}

__global__ void scanC_kernel() {
    __shared__ int sh[SCAN_B];
    int t = threadIdx.x;
    int i = blockIdx.x * SCAN_B + t;
    int v = (i < NN) ? g_deg[i] : 0;
    sh[t] = v;
    __syncthreads();
#pragma unroll
    for (int off = 1; off < SCAN_B; off <<= 1) {
        int x = (t >= off) ? sh[t - off] : 0;
        __syncthreads();
        sh[t] += x;
        __syncthreads();
    }
    if (i < NN) g_rowptr[i] = sh[t] - v + g_boff[blockIdx.x];
    if (i == NN - 1) g_rowptr[NN] = EE;
}

__global__ void fill_kernel(const int* __restrict__ ei, const float* __restrict__ ew) {
    int e = blockIdx.x * blockDim.x + threadIdx.x;
    if (e >= EE) return;
    int row = ei[e];
    int col = ei[EE + e];
    float en = ew[e] / fmaxf(g_wsum[row], 1.0f);
    int pos = g_rowptr[col] + atomicAdd(&g_cursor[col], 1);
    g_edge[pos] = make_float2(__int_as_float(row), en);
}

// ----------------------------------------------------------------------------
// Stem SGEMM (fp32 compute). LAYER 0 -> g_h1 (fp32). LAYER 1 -> g_xsh[0] (fp16, +res)
// ----------------------------------------------------------------------------
template <int LAYER>
__global__ void gemm128_kernel(const float* __restrict__ Xext) {
    const float* __restrict__ X  = (LAYER == 0) ? Xext : g_h1;
    const float* __restrict__ Wt = (LAYER == 0) ? g_Wt1 : g_Wt2;
    const float* __restrict__ A  = (LAYER == 0) ? g_A1 : g_A2;
    const float* __restrict__ C  = (LAYER == 0) ? g_C1 : g_C2;

    __shared__ float As[8][128];
    __shared__ float Bs[8][128];
    int tid = threadIdx.x;
    int m0 = blockIdx.x * 128;
    int ty = tid >> 4, tx = tid & 15;
    float acc[8][8];
#pragma unroll
    for (int i = 0; i < 8; ++i)
#pragma unroll
        for (int j = 0; j < 8; ++j) acc[i][j] = 0.f;

    int lr = tid >> 1;
    int lq = (tid & 1) * 4;
    int bkr = tid >> 5;
    int bnc = (tid & 31) * 4;

    for (int kc = 0; kc < 128; kc += 8) {
        float4 av = make_float4(0.f, 0.f, 0.f, 0.f);
        int gm = m0 + lr;
        if (gm < NN) av = *(const float4*)(X + (size_t)gm * 128 + kc + lq);
        As[lq + 0][lr] = av.x; As[lq + 1][lr] = av.y;
        As[lq + 2][lr] = av.z; As[lq + 3][lr] = av.w;
        *(float4*)&Bs[bkr][bnc] = *(const float4*)(Wt + (size_t)(kc + bkr) * 128 + bnc);
        __syncthreads();
#pragma unroll
        for (int k = 0; k < 8; ++k) {
            float a[8], b[8];
            *(float4*)(a)     = *(const float4*)&As[k][ty * 8];
            *(float4*)(a + 4) = *(const float4*)&As[k][ty * 8 + 4];
            *(float4*)(b)     = *(const float4*)&Bs[k][tx * 8];
            *(float4*)(b + 4) = *(const float4*)&Bs[k][tx * 8 + 4];
#pragma unroll
            for (int i = 0; i < 8; ++i)
#pragma unroll
                for (int j = 0; j < 8; ++j) acc[i][j] += a[i] * b[j];
        }
        __syncthreads();
    }
#pragma unroll
    for (int i = 0; i < 8; ++i) {
        int m = m0 + ty * 8 + i;
        if (m < NN) {
#pragma unroll
            for (int j = 0; j < 8; ++j) {
                int n = tx * 8 + j;
                float v = fmaxf(acc[i][j] * A[n] + C[n], 0.f);
                if (LAYER == 0) {
                    g_h1[(size_t)m * 128 + n] = v;
                } else {
                    v += X[(size_t)m * 128 + n];   // residual (g_h1)
                    g_xsh[(size_t)m * 128 + n] = __float2half_rn(v);
                }
            }
        }
    }
}

// ----------------------------------------------------------------------------
// Propagation: warp per node, fp16 gather (256B/edge), fp32 accumulate
// ----------------------------------------------------------------------------
__global__ void propagate_kernel(int k) {
    const size_t layer = (size_t)NN * HID;
    const uint2* __restrict__ hin2 = (const uint2*)(g_xsh + (size_t)k * layer);
    uint2* __restrict__ hout2 = (uint2*)(g_xsh + (size_t)(k + 1) * layer);
    const uint2* __restrict__ base2 = (const uint2*)g_xsh;

    int gt = blockIdx.x * blockDim.x + threadIdx.x;
    int node = gt >> 5;
    int lane = gt & 31;
    if (node >= NN) return;
    int s = g_rowptr[node];
    int e = g_rowptr[node + 1];
    float4 acc0 = make_float4(0.f, 0.f, 0.f, 0.f);
    float4 acc1 = make_float4(0.f, 0.f, 0.f, 0.f);
    int i = s;
    for (; i + 1 < e; i += 2) {
        float2 e0 = g_edge[i];
        float2 e1 = g_edge[i + 1];
        int s0 = __float_as_int(e0.x);
        int s1 = __float_as_int(e1.x);
        uint2 r0 = hin2[(size_t)s0 * 32 + lane];
        uint2 r1 = hin2[(size_t)s1 * 32 + lane];
        float4 v0 = h4_to_f4(r0);
        float4 v1 = h4_to_f4(r1);
        acc0.x += e0.y * v0.x; acc0.y += e0.y * v0.y; acc0.z += e0.y * v0.z; acc0.w += e0.y * v0.w;
        acc1.x += e1.y * v1.x; acc1.y += e1.y * v1.y; acc1.z += e1.y * v1.z; acc1.w += e1.y * v1.w;
    }
    if (i < e) {
        float2 e0 = g_edge[i];
        int s0 = __float_as_int(e0.x);
        float4 v0 = h4_to_f4(hin2[(size_t)s0 * 32 + lane]);
        acc0.x += e0.y * v0.x; acc0.y += e0.y * v0.y; acc0.z += e0.y * v0.z; acc0.w += e0.y * v0.w;
    }
    float4 b = h4_to_f4(base2[(size_t)node * 32 + lane]);
    float4 o;
    o.x = (1.f - ALPHA) * (acc0.x + acc1.x) + ALPHA * b.x;
    o.y = (1.f - ALPHA) * (acc0.y + acc1.y) + ALPHA * b.y;
    o.z = (1.f - ALPHA) * (acc0.z + acc1.z) + ALPHA * b.z;
    o.w = (1.f - ALPHA) * (acc0.w + acc1.w) + ALPHA * b.w;
    hout2[(size_t)node * 32 + lane] = f4_to_h4(o);
}

// ----------------------------------------------------------------------------
// Merged attention + hop fusion + head MLP
// ----------------------------------------------------------------------------
__global__ void att_head_kernel(const float* __restrict__ att1_b,
                                const float* __restrict__ att2_w,
                                const float* __restrict__ att2_b,
                                const float* __restrict__ head2_b,
                                float* __restrict__ out) {
    __shared__ float ctx_sh[8][2 * HID];
    __shared__ float a1_sh[8][AH];
    __shared__ float fsh[8][HID];
    __shared__ float zsh[8][HID / 2];
    int w = threadIdx.x >> 5;
    int lane = threadIdx.x & 31;
    int node = blockIdx.x * 8 + w;
    if (node >= NN) return;

    const size_t layer = (size_t)NN * HID;
    // ---- attention ----
    const uint2* x0 = (const uint2*)g_xsh;
    const uint2* xK = (const uint2*)(g_xsh + (size_t)KHOP * layer);
    float4 v0 = h4_to_f4(x0[(size_t)node * 32 + lane]);
    float4 vK = h4_to_f4(xK[(size_t)node * 32 + lane]);
    *(float4*)&ctx_sh[w][lane * 4] = v0;
    *(float4*)&ctx_sh[w][HID + lane * 4] = vK;
    __syncwarp();

    float2 acc = make_float2(0.f, 0.f);
    const float2* W2 = (const float2*)g_attWt1;
#pragma unroll 8
    for (int c = 0; c < 2 * HID; ++c) {
        float xv = ctx_sh[w][c];
        float2 wv = W2[c * (AH / 2) + lane];
        acc.x += xv * wv.x;
        acc.y += xv * wv.y;
    }
    float z0 = acc.x + att1_b[2 * lane];
    float z1 = acc.y + att1_b[2 * lane + 1];
    float g0 = 0.5f * z0 * (1.f + erff(z0 * 0.7071067811865475f));
    float g1 = 0.5f * z1 * (1.f + erff(z1 * 0.7071067811865475f));
    a1_sh[w][2 * lane] = g0;
    a1_sh[w][2 * lane + 1] = g1;
    __syncwarp();

    float logit = -INFINITY;
    if (lane < KHOP + 1) {
        float s = att2_b[lane];
#pragma unroll 8
        for (int c = 0; c < AH; ++c) s += a1_sh[w][c] * att2_w[lane * AH + c];
        logit = s;
    }
    float m = logit;
#pragma unroll
    for (int off = 16; off; off >>= 1) m = fmaxf(m, __shfl_xor_sync(0xffffffffu, m, off));
    float p = (lane < KHOP + 1) ? expf(logit - m) : 0.f;
    float sum = p;
#pragma unroll
    for (int off = 16; off; off >>= 1) sum += __shfl_xor_sync(0xffffffffu, sum, off);
    float prob = p / sum;

    float wk[KHOP + 1];
#pragma unroll
    for (int k = 0; k <= KHOP; ++k) wk[k] = __shfl_sync(0xffffffffu, prob, k);

    // ---- hop fusion ----
    float4 f = make_float4(0.f, 0.f, 0.f, 0.f);
#pragma unroll
    for (int k = 0; k <= KHOP; ++k) {
        const uint2* xk = (const uint2*)(g_xsh + (size_t)k * layer);
        float4 v = h4_to_f4(xk[(size_t)node * 32 + lane]);
        f.x += wk[k] * v.x; f.y += wk[k] * v.y; f.z += wk[k] * v.z; f.w += wk[k] * v.w;
    }
    *(float4*)&fsh[w][lane * 4] = f;
    __syncwarp();

    // ---- head1: 128 -> 64 ----
    float2 acch = make_float2(0.f, 0.f);
    const float2* H1 = (const float2*)g_h1Wt;
#pragma unroll 8
    for (int c = 0; c < HID; ++c) {
        float xv = fsh[w][c];
        float2 wv = H1[c * (HID / 4) + lane];
        acch.x += xv * wv.x;
        acch.y += xv * wv.y;
    }
    zsh[w][2 * lane]     = fmaxf(acch.x * g_A3[2 * lane] + g_C3[2 * lane], 0.f);
    zsh[w][2 * lane + 1] = fmaxf(acch.y * g_A3[2 * lane + 1] + g_C3[2 * lane + 1], 0.f);
    __syncwarp();

    // ---- head2: 64 -> 40 ----
    if (lane < OUT_DIM / 2) {
        float2 acc2 = make_float2(0.f, 0.f);
        const float2* H2 = (const float2*)g_h2Wt;
#pragma unroll 8
        for (int c = 0; c < HID / 2; ++c) {
            float zv = zsh[w][c];
            float2 wv = H2[c * (OUT_DIM / 2) + lane];
            acc2.x += zv * wv.x;
            acc2.y += zv * wv.y;
        }
        acc2.x += head2_b[2 * lane];
        acc2.y += head2_b[2 * lane + 1];
        *(float2*)(out + (size_t)node * OUT_DIM + 2 * lane) = acc2;
    }
}

// ----------------------------------------------------------------------------
// Launch
// ----------------------------------------------------------------------------
extern "C" void kernel_launch(void* const* d_in, const int* in_sizes, int n_in,
                              void* d_out, int out_size) {
    const float* x       = (const float*)d_in[0];
    const int*   ei      = (const int*)d_in[1];      // int32 [2, E]
    const float* ew      = (const float*)d_in[2];
    const float* lin1_w  = (const float*)d_in[3];
    const float* lin1_b  = (const float*)d_in[4];
    const float* bn1_g   = (const float*)d_in[5];
    const float* bn1_b   = (const float*)d_in[6];
    const float* bn1_m   = (const float*)d_in[7];
    const float* bn1_v   = (const float*)d_in[8];
    const float* lin2_w  = (const float*)d_in[9];
    const float* lin2_b  = (const float*)d_in[10];
    const float* bn2_g   = (const float*)d_in[11];
    const float* bn2_b   = (const float*)d_in[12];
    const float* bn2_m   = (const float*)d_in[13];
    const float* bn2_v   = (const float*)d_in[14];
    const float* att1_w  = (const float*)d_in[15];
    const float* att1_b  = (const float*)d_in[16];
    const float* att2_w  = (const float*)d_in[17];
    const float* att2_b  = (const float*)d_in[18];
    const float* head1_w = (const float*)d_in[19];
    const float* head1_b = (const float*)d_in[20];
    const float* bn3_g   = (const float*)d_in[21];
    const float* bn3_b   = (const float*)d_in[22];
    const float* bn3_m   = (const float*)d_in[23];
    const float* bn3_v   = (const float*)d_in[24];
    const float* head2_w = (const float*)d_in[25];
    const float* head2_b = (const float*)d_in[26];
    float* out = (float*)d_out;

    zero_kernel<<<(NN + 255) / 256, 256>>>();
    prep_kernel<<<(2 * HID * AH + 255) / 256, 256>>>(
        lin1_w, lin1_b, bn1_g, bn1_b, bn1_m, bn1_v,
        lin2_w, lin2_b, bn2_g, bn2_b, bn2_m, bn2_v,
        att1_w, head1_w, head1_b, bn3_g, bn3_b, bn3_m, bn3_v, head2_w);

    count_kernel<<<(EE + 255) / 256, 256>>>(ei, ew);
    scanA_kernel<<<SCAN_NB, SCAN_B>>>();
    scanB_kernel<<<1, SCAN_NB>>>();
    scanC_kernel<<<SCAN_NB, SCAN_B>>>();
    fill_kernel<<<(EE + 255) / 256, 256>>>(ei, ew);

    gemm128_kernel<0><<<(NN + 127) / 128, 256>>>(x);
    gemm128_kernel<1><<<(NN + 127) / 128, 256>>>(nullptr);

    for (int k = 0; k < KHOP; ++k) {
        propagate_kernel<<<(NN * 32 + 255) / 256, 256>>>(k);
    }

    att_head_kernel<<<(NN + 7) / 8, 256>>>(att1_b, att2_w, att2_b, head2_b, out);
}

// round 8
// speedup vs baseline: 1.3410x; 1.3410x over previous
#include <cuda_runtime.h>
#include <math.h>
#include <stdint.h>

#define NN 50000
#define EE 800000
#define IN_DIM 128
#define HID 128
#define OUT_DIM 40
#define KHOP 10
#define AH 64
#define ALPHA 0.1f
#define EPS 1e-5f

#define SCAN_B 256
#define SCAN_NB ((NN + SCAN_B - 1) / SCAN_B)   // 196

// ----------------------------------------------------------------------------
// Static device scratch
// ----------------------------------------------------------------------------
__device__ float g_xs[(KHOP + 1) * (size_t)NN * HID];   // 281.6 MB: h at every hop
__device__ float g_wsum[NN];
__device__ int   g_deg[NN];
__device__ int   g_rowptr[NN + 1];
__device__ int   g_cursor[NN];
__device__ int   g_bsum[SCAN_NB];
__device__ int   g_boff[SCAN_NB];
__device__ float2 g_edge[EE];                            // {src bits, enorm} CSR by dest

// transposed weights + folded BN constants
__device__ float g_Wt1[IN_DIM * HID];    // [k][n]
__device__ float g_Wt2[HID * HID];       // [k][n]
__device__ float g_attWt1[2 * HID * AH]; // [c][o]
__device__ float g_h1Wt[HID * (HID / 2)];// [c][o]  128x64
__device__ float g_h2Wt[(HID / 2) * OUT_DIM]; // [c][o] 64x40
__device__ float g_A1[HID], g_C1[HID], g_A2[HID], g_C2[HID], g_A3[HID / 2], g_C3[HID / 2];

// ----------------------------------------------------------------------------
// Prep
// ----------------------------------------------------------------------------
__global__ void zero_kernel() {
    int i = blockIdx.x * blockDim.x + threadIdx.x;
    if (i < NN) { g_wsum[i] = 0.f; g_deg[i] = 0; g_cursor[i] = 0; }
}

__global__ void prep_kernel(const float* __restrict__ lin1_w, const float* __restrict__ lin1_b,
                            const float* __restrict__ bn1_g, const float* __restrict__ bn1_b,
                            const float* __restrict__ bn1_m, const float* __restrict__ bn1_v,
                            const float* __restrict__ lin2_w, const float* __restrict__ lin2_b,
                            const float* __restrict__ bn2_g, const float* __restrict__ bn2_b,
                            const float* __restrict__ bn2_m, const float* __restrict__ bn2_v,
                            const float* __restrict__ att1_w,
                            const float* __restrict__ head1_w, const float* __restrict__ head1_b,
                            const float* __restrict__ bn3_g, const float* __restrict__ bn3_b,
                            const float* __restrict__ bn3_m, const float* __restrict__ bn3_v,
                            const float* __restrict__ head2_w) {
    int tid = blockIdx.x * blockDim.x + threadIdx.x;
    if (tid < IN_DIM * HID) {
        int k = tid >> 7, n = tid & 127;
        g_Wt1[tid] = lin1_w[n * IN_DIM + k];
        g_Wt2[tid] = lin2_w[n * HID + k];
    }
    if (tid < 2 * HID * AH) {
        int c = tid >> 6, o = tid & 63;
        g_attWt1[tid] = att1_w[o * (2 * HID) + c];
    }
    if (tid < HID * (HID / 2)) {
        int c = tid >> 6, o = tid & 63;
        g_h1Wt[tid] = head1_w[o * HID + c];
    }
    if (tid < (HID / 2) * OUT_DIM) {
        int c = tid / OUT_DIM, o = tid % OUT_DIM;
        g_h2Wt[tid] = head2_w[o * (HID / 2) + c];
    }
    if (tid < HID) {
        float a1 = bn1_g[tid] * rsqrtf(bn1_v[tid] + EPS);
        g_A1[tid] = a1;
        g_C1[tid] = lin1_b[tid] * a1 + bn1_b[tid] - bn1_m[tid] * a1;
        float a2 = bn2_g[tid] * rsqrtf(bn2_v[tid] + EPS);
        g_A2[tid] = a2;
        g_C2[tid] = lin2_b[tid] * a2 + bn2_b[tid] - bn2_m[tid] * a2;
    }
    if (tid < HID / 2) {
        float a3 = bn3_g[tid] * rsqrtf(bn3_v[tid] + EPS);
        g_A3[tid] = a3;
        g_C3[tid] = head1_b[tid] * a3 + bn3_b[tid] - bn3_m[tid] * a3;
    }
}

// ----------------------------------------------------------------------------
// Graph preprocessing
// ----------------------------------------------------------------------------
__global__ void count_kernel(const int* __restrict__ ei, const float* __restrict__ ew) {
    int e = blockIdx.x * blockDim.x + threadIdx.x;
    if (e >= EE) return;
    int row = ei[e];
    int col = ei[EE + e];
    atomicAdd(&g_wsum[row], ew[e]);
    atomicAdd(&g_deg[col], 1);
}

__global__ void scanA_kernel() {
    __shared__ int sh[SCAN_B];
    int t = threadIdx.x;
    int i = blockIdx.x * SCAN_B + t;
    int v = (i < NN) ? g_deg[i] : 0;
    sh[t] = v;
    __syncthreads();
#pragma unroll
    for (int off = SCAN_B / 2; off > 0; off >>= 1) {
        if (t < off) sh[t] += sh[t + off];
        __syncthreads();
    }
    if (t == 0) g_bsum[blockIdx.x] = sh[0];
}

__global__ void scanB_kernel() {
    __shared__ int sh[SCAN_NB];
    int t = threadIdx.x;
    int v = (t < SCAN_NB) ? g_bsum[t] : 0;
    if (t < SCAN_NB) sh[t] = v;
    __syncthreads();
    for (int off = 1; off < SCAN_NB; off <<= 1) {
        int x = (t < SCAN_NB && t >= off) ? sh[t - off] : 0;
        __syncthreads();
        if (t < SCAN_NB) sh[t] += x;
        __syncthreads();
    }
    if (t < SCAN_NB) g_boff[t] = sh[t] - v;  // exclusive
}

__global__ void scanC_kernel() {
    __shared__ int sh[SCAN_B];
    int t = threadIdx.x;
    int i = blockIdx.x * SCAN_B + t;
    int v = (i < NN) ? g_deg[i] : 0;
    sh[t] = v;
    __syncthreads();
#pragma unroll
    for (int off = 1; off < SCAN_B; off <<= 1) {
        int x = (t >= off) ? sh[t - off] : 0;
        __syncthreads();
        sh[t] += x;
        __syncthreads();
    }
    if (i < NN) g_rowptr[i] = sh[t] - v + g_boff[blockIdx.x];
    if (i == NN - 1) g_rowptr[NN] = EE;
}

__global__ void fill_kernel(const int* __restrict__ ei, const float* __restrict__ ew) {
    int e = blockIdx.x * blockDim.x + threadIdx.x;
    if (e >= EE) return;
    int row = ei[e];
    int col = ei[EE + e];
    float en = ew[e] / fmaxf(g_wsum[row], 1.0f);
    int pos = g_rowptr[col] + atomicAdd(&g_cursor[col], 1);
    g_edge[pos] = make_float2(__int_as_float(row), en);
}

// ----------------------------------------------------------------------------
// Fused stem: both GEMMs in one kernel. BM=64 rows/block.
// Phase 1: h1 = relu(bn1(x @ W1^T))            -> kept in smem [64][129]
// Phase 2: xs0 = relu(bn2(h1 @ W2^T)) + h1     -> written to g_xs[0]
// 256 threads: (ty 0..15) x (tx 0..15), micro-tile 4x8 per thread.
// ----------------------------------------------------------------------------
__global__ __launch_bounds__(256) void stem_kernel(const float* __restrict__ X) {
    __shared__ float As[8][64];
    __shared__ float Bs[8][128];
    __shared__ float H1[64][129];   // padded: stride 129 avoids phase-2 bank conflicts

    int tid = threadIdx.x;
    int m0 = blockIdx.x * 64;
    int ty = tid >> 4, tx = tid & 15;     // 16x16 threads

    float acc[4][8];
#pragma unroll
    for (int i = 0; i < 4; ++i)
#pragma unroll
        for (int j = 0; j < 8; ++j) acc[i][j] = 0.f;

    // ---- Phase 1: X(global) @ Wt1 ----
    int lr = tid >> 2;            // 0..63 row for A load
    int lq = (tid & 3) * 2;       // k sub-offset (float2)
    int bkr = tid >> 5;           // 0..7 k row for B load
    int bnc = (tid & 31) * 4;     // n offset (float4)

    for (int kc = 0; kc < 128; kc += 8) {
        float2 av = make_float2(0.f, 0.f);
        int gm = m0 + lr;
        if (gm < NN) av = *(const float2*)(X + (size_t)gm * 128 + kc + lq);
        As[lq + 0][lr] = av.x;
        As[lq + 1][lr] = av.y;
        *(float4*)&Bs[bkr][bnc] = *(const float4*)(g_Wt1 + (size_t)(kc + bkr) * 128 + bnc);
        __syncthreads();
#pragma unroll
        for (int k = 0; k < 8; ++k) {
            float a[4], b[8];
            *(float4*)(a)     = *(const float4*)&As[k][ty * 4];
            *(float4*)(b)     = *(const float4*)&Bs[k][tx * 8];
            *(float4*)(b + 4) = *(const float4*)&Bs[k][tx * 8 + 4];
#pragma unroll
            for (int i = 0; i < 4; ++i)
#pragma unroll
                for (int j = 0; j < 8; ++j) acc[i][j] += a[i] * b[j];
        }
        __syncthreads();
    }
    // epilogue 1 -> smem
#pragma unroll
    for (int i = 0; i < 4; ++i) {
#pragma unroll
        for (int j = 0; j < 8; ++j) {
            int n = tx * 8 + j;
            H1[ty * 4 + i][n] = fmaxf(acc[i][j] * g_A1[n] + g_C1[n], 0.f);
        }
    }
    __syncthreads();

    // ---- Phase 2: H1(smem) @ Wt2 ----
#pragma unroll
    for (int i = 0; i < 4; ++i)
#pragma unroll
        for (int j = 0; j < 8; ++j) acc[i][j] = 0.f;

    for (int kc = 0; kc < 128; kc += 8) {
        *(float4*)&Bs[bkr][bnc] = *(const float4*)(g_Wt2 + (size_t)(kc + bkr) * 128 + bnc);
        __syncthreads();
#pragma unroll
        for (int k = 0; k < 8; ++k) {
            float a[4], b[8];
#pragma unroll
            for (int i = 0; i < 4; ++i) a[i] = H1[ty * 4 + i][kc + k];
            *(float4*)(b)     = *(const float4*)&Bs[k][tx * 8];
            *(float4*)(b + 4) = *(const float4*)&Bs[k][tx * 8 + 4];
#pragma unroll
            for (int i = 0; i < 4; ++i)
#pragma unroll
                for (int j = 0; j < 8; ++j) acc[i][j] += a[i] * b[j];
        }
        __syncthreads();
    }
    // epilogue 2: bn2+relu+residual -> g_xs[0]
#pragma unroll
    for (int i = 0; i < 4; ++i) {
        int m = m0 + ty * 4 + i;
        if (m < NN) {
#pragma unroll
            for (int j = 0; j < 8; ++j) {
                int n = tx * 8 + j;
                float v = fmaxf(acc[i][j] * g_A2[n] + g_C2[n], 0.f) + H1[ty * 4 + i][n];
                g_xs[(size_t)m * 128 + n] = v;
            }
        }
    }
}

// ----------------------------------------------------------------------------
// Propagation: warp per node, CSR, no atomics, unroll x2
// ----------------------------------------------------------------------------
__global__ void propagate_kernel(int k) {
    const size_t layer = (size_t)NN * HID;
    const float* __restrict__ hin = g_xs + (size_t)k * layer;
    float* __restrict__ hout = g_xs + (size_t)(k + 1) * layer;

    int gt = blockIdx.x * blockDim.x + threadIdx.x;
    int node = gt >> 5;
    int lane = gt & 31;
    if (node >= NN) return;
    int s = g_rowptr[node];
    int e = g_rowptr[node + 1];
    const float4* __restrict__ hin4 = (const float4*)hin;
    float4 acc0 = make_float4(0.f, 0.f, 0.f, 0.f);
    float4 acc1 = make_float4(0.f, 0.f, 0.f, 0.f);
    int i = s;
    for (; i + 1 < e; i += 2) {
        float2 e0 = g_edge[i];
        float2 e1 = g_edge[i + 1];
        int s0 = __float_as_int(e0.x);
        int s1 = __float_as_int(e1.x);
        float4 v0 = hin4[(size_t)s0 * 32 + lane];
        float4 v1 = hin4[(size_t)s1 * 32 + lane];
        acc0.x += e0.y * v0.x; acc0.y += e0.y * v0.y; acc0.z += e0.y * v0.z; acc0.w += e0.y * v0.w;
        acc1.x += e1.y * v1.x; acc1.y += e1.y * v1.y; acc1.z += e1.y * v1.z; acc1.w += e1.y * v1.w;
    }
    if (i < e) {
        float2 e0 = g_edge[i];
        int s0 = __float_as_int(e0.x);
        float4 v0 = hin4[(size_t)s0 * 32 + lane];
        acc0.x += e0.y * v0.x; acc0.y += e0.y * v0.y; acc0.z += e0.y * v0.z; acc0.w += e0.y * v0.w;
    }
    float4 b = ((const float4*)g_xs)[(size_t)node * 32 + lane];
    float4 o;
    o.x = (1.f - ALPHA) * (acc0.x + acc1.x) + ALPHA * b.x;
    o.y = (1.f - ALPHA) * (acc0.y + acc1.y) + ALPHA * b.y;
    o.z = (1.f - ALPHA) * (acc0.z + acc1.z) + ALPHA * b.z;
    o.w = (1.f - ALPHA) * (acc0.w + acc1.w) + ALPHA * b.w;
    ((float4*)hout)[(size_t)node * 32 + lane] = o;
}

// ----------------------------------------------------------------------------
// Merged attention + hop fusion + head MLP
// ----------------------------------------------------------------------------
__global__ void att_head_kernel(const float* __restrict__ att1_b,
                                const float* __restrict__ att2_w,
                                const float* __restrict__ att2_b,
                                const float* __restrict__ head2_b,
                                float* __restrict__ out) {
    __shared__ float ctx_sh[8][2 * HID];
    __shared__ float a1_sh[8][AH];
    __shared__ float fsh[8][HID];
    __shared__ float zsh[8][HID / 2];
    int w = threadIdx.x >> 5;
    int lane = threadIdx.x & 31;
    int node = blockIdx.x * 8 + w;
    if (node >= NN) return;

    // ---- attention ----
    const float4* x0 = (const float4*)g_xs;
    const float4* xK = (const float4*)(g_xs + (size_t)KHOP * NN * HID);
    float4 v0 = x0[(size_t)node * 32 + lane];
    float4 vK = xK[(size_t)node * 32 + lane];
    *(float4*)&ctx_sh[w][lane * 4] = v0;
    *(float4*)&ctx_sh[w][HID + lane * 4] = vK;
    __syncwarp();

    float2 acc = make_float2(0.f, 0.f);
    const float2* W2 = (const float2*)g_attWt1;
#pragma unroll 8
    for (int c = 0; c < 2 * HID; ++c) {
        float xv = ctx_sh[w][c];
        float2 wv = W2[c * (AH / 2) + lane];
        acc.x += xv * wv.x;
        acc.y += xv * wv.y;
    }
    float z0 = acc.x + att1_b[2 * lane];
    float z1 = acc.y + att1_b[2 * lane + 1];
    float g0 = 0.5f * z0 * (1.f + erff(z0 * 0.7071067811865475f));
    float g1 = 0.5f * z1 * (1.f + erff(z1 * 0.7071067811865475f));
    a1_sh[w][2 * lane] = g0;
    a1_sh[w][2 * lane + 1] = g1;
    __syncwarp();

    float logit = -INFINITY;
    if (lane < KHOP + 1) {
        float s = att2_b[lane];
#pragma unroll 8
        for (int c = 0; c < AH; ++c) s += a1_sh[w][c] * att2_w[lane * AH + c];
        logit = s;
    }
    float m = logit;
#pragma unroll
    for (int off = 16; off; off >>= 1) m = fmaxf(m, __shfl_xor_sync(0xffffffffu, m, off));
    float p = (lane < KHOP + 1) ? expf(logit - m) : 0.f;
    float sum = p;
#pragma unroll
    for (int off = 16; off; off >>= 1) sum += __shfl_xor_sync(0xffffffffu, sum, off);
    float prob = p / sum;

    float wk[KHOP + 1];
#pragma unroll
    for (int k = 0; k <= KHOP; ++k) wk[k] = __shfl_sync(0xffffffffu, prob, k);

    // ---- hop fusion ----
    float4 f = make_float4(0.f, 0.f, 0.f, 0.f);
#pragma unroll
    for (int k = 0; k <= KHOP; ++k) {
        const float4* xk = (const float4*)(g_xs + (size_t)k * NN * HID);
        float4 v = xk[(size_t)node * 32 + lane];
        f.x += wk[k] * v.x; f.y += wk[k] * v.y; f.z += wk[k] * v.z; f.w += wk[k] * v.w;
    }
    *(float4*)&fsh[w][lane * 4] = f;
    __syncwarp();

    // ---- head1: 128 -> 64 ----
    float2 acch = make_float2(0.f, 0.f);
    const float2* H1 = (const float2*)g_h1Wt;
#pragma unroll 8
    for (int c = 0; c < HID; ++c) {
        float xv = fsh[w][c];
        float2 wv = H1[c * (HID / 4) + lane];
        acch.x += xv * wv.x;
        acch.y += xv * wv.y;
    }
    zsh[w][2 * lane]     = fmaxf(acch.x * g_A3[2 * lane] + g_C3[2 * lane], 0.f);
    zsh[w][2 * lane + 1] = fmaxf(acch.y * g_A3[2 * lane + 1] + g_C3[2 * lane + 1], 0.f);
    __syncwarp();

    // ---- head2: 64 -> 40 ----
    if (lane < OUT_DIM / 2) {
        float2 acc2 = make_float2(0.f, 0.f);
        const float2* H2 = (const float2*)g_h2Wt;
#pragma unroll 8
        for (int c = 0; c < HID / 2; ++c) {
            float zv = zsh[w][c];
            float2 wv = H2[c * (OUT_DIM / 2) + lane];
            acc2.x += zv * wv.x;
            acc2.y += zv * wv.y;
        }
        acc2.x += head2_b[2 * lane];
        acc2.y += head2_b[2 * lane + 1];
        *(float2*)(out + (size_t)node * OUT_DIM + 2 * lane) = acc2;
    }
}

// ----------------------------------------------------------------------------
// Launch
// ----------------------------------------------------------------------------
extern "C" void kernel_launch(void* const* d_in, const int* in_sizes, int n_in,
                              void* d_out, int out_size) {
    const float* x       = (const float*)d_in[0];
    const int*   ei      = (const int*)d_in[1];      // int32 [2, E]
    const float* ew      = (const float*)d_in[2];
    const float* lin1_w  = (const float*)d_in[3];
    const float* lin1_b  = (const float*)d_in[4];
    const float* bn1_g   = (const float*)d_in[5];
    const float* bn1_b   = (const float*)d_in[6];
    const float* bn1_m   = (const float*)d_in[7];
    const float* bn1_v   = (const float*)d_in[8];
    const float* lin2_w  = (const float*)d_in[9];
    const float* lin2_b  = (const float*)d_in[10];
    const float* bn2_g   = (const float*)d_in[11];
    const float* bn2_b   = (const float*)d_in[12];
    const float* bn2_m   = (const float*)d_in[13];
    const float* bn2_v   = (const float*)d_in[14];
    const float* att1_w  = (const float*)d_in[15];
    const float* att1_b  = (const float*)d_in[16];
    const float* att2_w  = (const float*)d_in[17];
    const float* att2_b  = (const float*)d_in[18];
    const float* head1_w = (const float*)d_in[19];
    const float* head1_b = (const float*)d_in[20];
    const float* bn3_g   = (const float*)d_in[21];
    const float* bn3_b   = (const float*)d_in[22];
    const float* bn3_m   = (const float*)d_in[23];
    const float* bn3_v   = (const float*)d_in[24];
    const float* head2_w = (const float*)d_in[25];
    const float* head2_b = (const float*)d_in[26];
    float* out = (float*)d_out;

    zero_kernel<<<(NN + 255) / 256, 256>>>();
    prep_kernel<<<(2 * HID * AH + 255) / 256, 256>>>(
        lin1_w, lin1_b, bn1_g, bn1_b, bn1_m, bn1_v,
        lin2_w, lin2_b, bn2_g, bn2_b, bn2_m, bn2_v,
        att1_w, head1_w, head1_b, bn3_g, bn3_b, bn3_m, bn3_v, head2_w);

    count_kernel<<<(EE + 255) / 256, 256>>>(ei, ew);
    scanA_kernel<<<SCAN_NB, SCAN_B>>>();
    scanB_kernel<<<1, SCAN_NB>>>();
    scanC_kernel<<<SCAN_NB, SCAN_B>>>();
    fill_kernel<<<(EE + 255) / 256, 256>>>(ei, ew);

    stem_kernel<<<(NN + 63) / 64, 256>>>(x);

    for (int k = 0; k < KHOP; ++k) {
        propagate_kernel<<<(NN * 32 + 255) / 256, 256>>>(k);
    }

    att_head_kernel<<<(NN + 7) / 8, 256>>>(att1_b, att2_w, att2_b, head2_b, out);
}

// round 9
// speedup vs baseline: 1.3571x; 1.0120x over previous
#include <cuda_runtime.h>
#include <math.h>
#include <stdint.h>

#define NN 50000
#define EE 800000
#define IN_DIM 128
#define HID 128
#define OUT_DIM 40
#define KHOP 10
#define AH 64
#define ALPHA 0.1f
#define EPS 1e-5f

#define SCAN_B 256
#define SCAN_NB ((NN + SCAN_B - 1) / SCAN_B)   // 196

// ----------------------------------------------------------------------------
// Static device scratch
// ----------------------------------------------------------------------------
__device__ float g_xs[(KHOP + 1) * (size_t)NN * HID];   // 281.6 MB: h at every hop
__device__ float g_wsum[NN];
__device__ int   g_deg[NN];
__device__ int   g_rowptr[NN + 1];
__device__ int   g_cursor[NN];
__device__ int   g_bsum[SCAN_NB];
__device__ int   g_boff[SCAN_NB];
__device__ float2 g_edge[EE];                            // {src bits, enorm} CSR by dest

// transposed weights + folded BN constants
__device__ float g_Wt1[IN_DIM * HID];    // [k][n]
__device__ float g_Wt2[HID * HID];       // [k][n]
__device__ float g_attWt1[2 * HID * AH]; // [c][o]
__device__ float g_h1Wt[HID * (HID / 2)];// [c][o]  128x64
__device__ float g_h2Wt[(HID / 2) * OUT_DIM]; // [c][o] 64x40
__device__ float g_A1[HID], g_C1[HID], g_A2[HID], g_C2[HID], g_A3[HID / 2], g_C3[HID / 2];

// ----------------------------------------------------------------------------
// Prep
// ----------------------------------------------------------------------------
__global__ void zero_kernel() {
    int i = blockIdx.x * blockDim.x + threadIdx.x;
    if (i < NN) { g_wsum[i] = 0.f; g_deg[i] = 0; g_cursor[i] = 0; }
}

__global__ void prep_kernel(const float* __restrict__ lin1_w, const float* __restrict__ lin1_b,
                            const float* __restrict__ bn1_g, const float* __restrict__ bn1_b,
                            const float* __restrict__ bn1_m, const float* __restrict__ bn1_v,
                            const float* __restrict__ lin2_w, const float* __restrict__ lin2_b,
                            const float* __restrict__ bn2_g, const float* __restrict__ bn2_b,
                            const float* __restrict__ bn2_m, const float* __restrict__ bn2_v,
                            const float* __restrict__ att1_w,
                            const float* __restrict__ head1_w, const float* __restrict__ head1_b,
                            const float* __restrict__ bn3_g, const float* __restrict__ bn3_b,
                            const float* __restrict__ bn3_m, const float* __restrict__ bn3_v,
                            const float* __restrict__ head2_w) {
    int tid = blockIdx.x * blockDim.x + threadIdx.x;
    if (tid < IN_DIM * HID) {
        int k = tid >> 7, n = tid & 127;
        g_Wt1[tid] = lin1_w[n * IN_DIM + k];
        g_Wt2[tid] = lin2_w[n * HID + k];
    }
    if (tid < 2 * HID * AH) {
        int c = tid >> 6, o = tid & 63;
        g_attWt1[tid] = att1_w[o * (2 * HID) + c];
    }
    if (tid < HID * (HID / 2)) {
        int c = tid >> 6, o = tid & 63;
        g_h1Wt[tid] = head1_w[o * HID + c];
    }
    if (tid < (HID / 2) * OUT_DIM) {
        int c = tid / OUT_DIM, o = tid % OUT_DIM;
        g_h2Wt[tid] = head2_w[o * (HID / 2) + c];
    }
    if (tid < HID) {
        float a1 = bn1_g[tid] * rsqrtf(bn1_v[tid] + EPS);
        g_A1[tid] = a1;
        g_C1[tid] = lin1_b[tid] * a1 + bn1_b[tid] - bn1_m[tid] * a1;
        float a2 = bn2_g[tid] * rsqrtf(bn2_v[tid] + EPS);
        g_A2[tid] = a2;
        g_C2[tid] = lin2_b[tid] * a2 + bn2_b[tid] - bn2_m[tid] * a2;
    }
    if (tid < HID / 2) {
        float a3 = bn3_g[tid] * rsqrtf(bn3_v[tid] + EPS);
        g_A3[tid] = a3;
        g_C3[tid] = head1_b[tid] * a3 + bn3_b[tid] - bn3_m[tid] * a3;
    }
}

// ----------------------------------------------------------------------------
// Graph preprocessing
// ----------------------------------------------------------------------------
__global__ void count_kernel(const int* __restrict__ ei, const float* __restrict__ ew) {
    int e = blockIdx.x * blockDim.x + threadIdx.x;
    if (e >= EE) return;
    int row = ei[e];
    int col = ei[EE + e];
    atomicAdd(&g_wsum[row], ew[e]);
    atomicAdd(&g_deg[col], 1);
}

__global__ void scanA_kernel() {
    __shared__ int sh[SCAN_B];
    int t = threadIdx.x;
    int i = blockIdx.x * SCAN_B + t;
    int v = (i < NN) ? g_deg[i] : 0;
    sh[t] = v;
    __syncthreads();
#pragma unroll
    for (int off = SCAN_B / 2; off > 0; off >>= 1) {
        if (t < off) sh[t] += sh[t + off];
        __syncthreads();
    }
    if (t == 0) g_bsum[blockIdx.x] = sh[0];
}

__global__ void scanB_kernel() {
    __shared__ int sh[SCAN_NB];
    int t = threadIdx.x;
    int v = (t < SCAN_NB) ? g_bsum[t] : 0;
    if (t < SCAN_NB) sh[t] = v;
    __syncthreads();
    for (int off = 1; off < SCAN_NB; off <<= 1) {
        int x = (t < SCAN_NB && t >= off) ? sh[t - off] : 0;
        __syncthreads();
        if (t < SCAN_NB) sh[t] += x;
        __syncthreads();
    }
    if (t < SCAN_NB) g_boff[t] = sh[t] - v;  // exclusive
}

__global__ void scanC_kernel() {
    __shared__ int sh[SCAN_B];
    int t = threadIdx.x;
    int i = blockIdx.x * SCAN_B + t;
    int v = (i < NN) ? g_deg[i] : 0;
    sh[t] = v;
    __syncthreads();
#pragma unroll
    for (int off = 1; off < SCAN_B; off <<= 1) {
        int x = (t >= off) ? sh[t - off] : 0;
        __syncthreads();
        sh[t] += x;
        __syncthreads();
    }
    if (i < NN) g_rowptr[i] = sh[t] - v + g_boff[blockIdx.x];
    if (i == NN - 1) g_rowptr[NN] = EE;
}

__global__ void fill_kernel(const int* __restrict__ ei, const float* __restrict__ ew) {
    int e = blockIdx.x * blockDim.x + threadIdx.x;
    if (e >= EE) return;
    int row = ei[e];
    int col = ei[EE + e];
    float en = ew[e] / fmaxf(g_wsum[row], 1.0f);
    int pos = g_rowptr[col] + atomicAdd(&g_cursor[col], 1);
    g_edge[pos] = make_float2(__int_as_float(row), en);
}

// ----------------------------------------------------------------------------
// Fused stem: both GEMMs in one kernel. BM=64 rows/block.
// ----------------------------------------------------------------------------
__global__ __launch_bounds__(256) void stem_kernel(const float* __restrict__ X) {
    __shared__ float As[8][64];
    __shared__ float Bs[8][128];
    __shared__ float H1[64][129];

    int tid = threadIdx.x;
    int m0 = blockIdx.x * 64;
    int ty = tid >> 4, tx = tid & 15;

    float acc[4][8];
#pragma unroll
    for (int i = 0; i < 4; ++i)
#pragma unroll
        for (int j = 0; j < 8; ++j) acc[i][j] = 0.f;

    int lr = tid >> 2;
    int lq = (tid & 3) * 2;
    int bkr = tid >> 5;
    int bnc = (tid & 31) * 4;

    for (int kc = 0; kc < 128; kc += 8) {
        float2 av = make_float2(0.f, 0.f);
        int gm = m0 + lr;
        if (gm < NN) av = *(const float2*)(X + (size_t)gm * 128 + kc + lq);
        As[lq + 0][lr] = av.x;
        As[lq + 1][lr] = av.y;
        *(float4*)&Bs[bkr][bnc] = *(const float4*)(g_Wt1 + (size_t)(kc + bkr) * 128 + bnc);
        __syncthreads();
#pragma unroll
        for (int k = 0; k < 8; ++k) {
            float a[4], b[8];
            *(float4*)(a)     = *(const float4*)&As[k][ty * 4];
            *(float4*)(b)     = *(const float4*)&Bs[k][tx * 8];
            *(float4*)(b + 4) = *(const float4*)&Bs[k][tx * 8 + 4];
#pragma unroll
            for (int i = 0; i < 4; ++i)
#pragma unroll
                for (int j = 0; j < 8; ++j) acc[i][j] += a[i] * b[j];
        }
        __syncthreads();
    }
#pragma unroll
    for (int i = 0; i < 4; ++i) {
#pragma unroll
        for (int j = 0; j < 8; ++j) {
            int n = tx * 8 + j;
            H1[ty * 4 + i][n] = fmaxf(acc[i][j] * g_A1[n] + g_C1[n], 0.f);
        }
    }
    __syncthreads();

#pragma unroll
    for (int i = 0; i < 4; ++i)
#pragma unroll
        for (int j = 0; j < 8; ++j) acc[i][j] = 0.f;

    for (int kc = 0; kc < 128; kc += 8) {
        *(float4*)&Bs[bkr][bnc] = *(const float4*)(g_Wt2 + (size_t)(kc + bkr) * 128 + bnc);
        __syncthreads();
#pragma unroll
        for (int k = 0; k < 8; ++k) {
            float a[4], b[8];
#pragma unroll
            for (int i = 0; i < 4; ++i) a[i] = H1[ty * 4 + i][kc + k];
            *(float4*)(b)     = *(const float4*)&Bs[k][tx * 8];
            *(float4*)(b + 4) = *(const float4*)&Bs[k][tx * 8 + 4];
#pragma unroll
            for (int i = 0; i < 4; ++i)
#pragma unroll
                for (int j = 0; j < 8; ++j) acc[i][j] += a[i] * b[j];
        }
        __syncthreads();
    }
#pragma unroll
    for (int i = 0; i < 4; ++i) {
        int m = m0 + ty * 4 + i;
        if (m < NN) {
#pragma unroll
            for (int j = 0; j < 8; ++j) {
                int n = tx * 8 + j;
                float v = fmaxf(acc[i][j] * g_A2[n] + g_C2[n], 0.f) + H1[ty * 4 + i][n];
                g_xs[(size_t)m * 128 + n] = v;
            }
        }
    }
}

// ----------------------------------------------------------------------------
// Propagation: warp per node, CSR, no atomics, unroll x4, L1-bypass gathers
// ----------------------------------------------------------------------------
__global__ void propagate_kernel(int k) {
    const size_t layer = (size_t)NN * HID;
    const float* __restrict__ hin = g_xs + (size_t)k * layer;
    float* __restrict__ hout = g_xs + (size_t)(k + 1) * layer;

    int gt = blockIdx.x * blockDim.x + threadIdx.x;
    int node = gt >> 5;
    int lane = gt & 31;
    if (node >= NN) return;
    int s = g_rowptr[node];
    int e = g_rowptr[node + 1];
    const float4* __restrict__ hin4 = (const float4*)hin;

    float4 acc0 = make_float4(0.f, 0.f, 0.f, 0.f);
    float4 acc1 = make_float4(0.f, 0.f, 0.f, 0.f);
    float4 acc2 = make_float4(0.f, 0.f, 0.f, 0.f);
    float4 acc3 = make_float4(0.f, 0.f, 0.f, 0.f);

    int deg = e - s;
    int i = s;
    int n4 = s + (deg & ~3);
    for (; i < n4; i += 4) {
        float2 e0 = g_edge[i];
        float2 e1 = g_edge[i + 1];
        float2 e2 = g_edge[i + 2];
        float2 e3 = g_edge[i + 3];
        int s0 = __float_as_int(e0.x);
        int s1 = __float_as_int(e1.x);
        int s2 = __float_as_int(e2.x);
        int s3 = __float_as_int(e3.x);
        float4 v0 = __ldcg(&hin4[(size_t)s0 * 32 + lane]);
        float4 v1 = __ldcg(&hin4[(size_t)s1 * 32 + lane]);
        float4 v2 = __ldcg(&hin4[(size_t)s2 * 32 + lane]);
        float4 v3 = __ldcg(&hin4[(size_t)s3 * 32 + lane]);
        acc0.x += e0.y * v0.x; acc0.y += e0.y * v0.y; acc0.z += e0.y * v0.z; acc0.w += e0.y * v0.w;
        acc1.x += e1.y * v1.x; acc1.y += e1.y * v1.y; acc1.z += e1.y * v1.z; acc1.w += e1.y * v1.w;
        acc2.x += e2.y * v2.x; acc2.y += e2.y * v2.y; acc2.z += e2.y * v2.z; acc2.w += e2.y * v2.w;
        acc3.x += e3.y * v3.x; acc3.y += e3.y * v3.y; acc3.z += e3.y * v3.z; acc3.w += e3.y * v3.w;
    }
    for (; i < e; ++i) {
        float2 e0 = g_edge[i];
        int s0 = __float_as_int(e0.x);
        float4 v0 = __ldcg(&hin4[(size_t)s0 * 32 + lane]);
        acc0.x += e0.y * v0.x; acc0.y += e0.y * v0.y; acc0.z += e0.y * v0.z; acc0.w += e0.y * v0.w;
    }
    float4 b = __ldcg(&((const float4*)g_xs)[(size_t)node * 32 + lane]);
    float4 o;
    o.x = (1.f - ALPHA) * ((acc0.x + acc1.x) + (acc2.x + acc3.x)) + ALPHA * b.x;
    o.y = (1.f - ALPHA) * ((acc0.y + acc1.y) + (acc2.y + acc3.y)) + ALPHA * b.y;
    o.z = (1.f - ALPHA) * ((acc0.z + acc1.z) + (acc2.z + acc3.z)) + ALPHA * b.z;
    o.w = (1.f - ALPHA) * ((acc0.w + acc1.w) + (acc2.w + acc3.w)) + ALPHA * b.w;
    ((float4*)hout)[(size_t)node * 32 + lane] = o;
}

// ----------------------------------------------------------------------------
// Merged attention + hop fusion + head MLP
// ----------------------------------------------------------------------------
__global__ void att_head_kernel(const float* __restrict__ att1_b,
                                const float* __restrict__ att2_w,
                                const float* __restrict__ att2_b,
                                const float* __restrict__ head2_b,
                                float* __restrict__ out) {
    __shared__ float ctx_sh[8][2 * HID];
    __shared__ float a1_sh[8][AH];
    __shared__ float fsh[8][HID];
    __shared__ float zsh[8][HID / 2];
    int w = threadIdx.x >> 5;
    int lane = threadIdx.x & 31;
    int node = blockIdx.x * 8 + w;
    if (node >= NN) return;

    // ---- attention ----
    const float4* x0 = (const float4*)g_xs;
    const float4* xK = (const float4*)(g_xs + (size_t)KHOP * NN * HID);
    float4 v0 = x0[(size_t)node * 32 + lane];
    float4 vK = xK[(size_t)node * 32 + lane];
    *(float4*)&ctx_sh[w][lane * 4] = v0;
    *(float4*)&ctx_sh[w][HID + lane * 4] = vK;
    __syncwarp();

    float2 acc = make_float2(0.f, 0.f);
    const float2* W2 = (const float2*)g_attWt1;
#pragma unroll 8
    for (int c = 0; c < 2 * HID; ++c) {
        float xv = ctx_sh[w][c];
        float2 wv = W2[c * (AH / 2) + lane];
        acc.x += xv * wv.x;
        acc.y += xv * wv.y;
    }
    float z0 = acc.x + att1_b[2 * lane];
    float z1 = acc.y + att1_b[2 * lane + 1];
    float g0 = 0.5f * z0 * (1.f + erff(z0 * 0.7071067811865475f));
    float g1 = 0.5f * z1 * (1.f + erff(z1 * 0.7071067811865475f));
    a1_sh[w][2 * lane] = g0;
    a1_sh[w][2 * lane + 1] = g1;
    __syncwarp();

    float logit = -INFINITY;
    if (lane < KHOP + 1) {
        float s = att2_b[lane];
#pragma unroll 8
        for (int c = 0; c < AH; ++c) s += a1_sh[w][c] * att2_w[lane * AH + c];
        logit = s;
    }
    float m = logit;
#pragma unroll
    for (int off = 16; off; off >>= 1) m = fmaxf(m, __shfl_xor_sync(0xffffffffu, m, off));
    float p = (lane < KHOP + 1) ? expf(logit - m) : 0.f;
    float sum = p;
#pragma unroll
    for (int off = 16; off; off >>= 1) sum += __shfl_xor_sync(0xffffffffu, sum, off);
    float prob = p / sum;

    float wk[KHOP + 1];
#pragma unroll
    for (int k = 0; k <= KHOP; ++k) wk[k] = __shfl_sync(0xffffffffu, prob, k);

    // ---- hop fusion (k=0 and k=KHOP reuse registers v0/vK) ----
    float4 f;
    f.x = wk[0] * v0.x + wk[KHOP] * vK.x;
    f.y = wk[0] * v0.y + wk[KHOP] * vK.y;
    f.z = wk[0] * v0.z + wk[KHOP] * vK.z;
    f.w = wk[0] * v0.w + wk[KHOP] * vK.w;
#pragma unroll
    for (int k = 1; k < KHOP; ++k) {
        const float4* xk = (const float4*)(g_xs + (size_t)k * NN * HID);
        float4 v = xk[(size_t)node * 32 + lane];
        f.x += wk[k] * v.x; f.y += wk[k] * v.y; f.z += wk[k] * v.z; f.w += wk[k] * v.w;
    }
    *(float4*)&fsh[w][lane * 4] = f;
    __syncwarp();

    // ---- head1: 128 -> 64 ----
    float2 acch = make_float2(0.f, 0.f);
    const float2* H1 = (const float2*)g_h1Wt;
#pragma unroll 8
    for (int c = 0; c < HID; ++c) {
        float xv = fsh[w][c];
        float2 wv = H1[c * (HID / 4) + lane];
        acch.x += xv * wv.x;
        acch.y += xv * wv.y;
    }
    zsh[w][2 * lane]     = fmaxf(acch.x * g_A3[2 * lane] + g_C3[2 * lane], 0.f);
    zsh[w][2 * lane + 1] = fmaxf(acch.y * g_A3[2 * lane + 1] + g_C3[2 * lane + 1], 0.f);
    __syncwarp();

    // ---- head2: 64 -> 40 ----
    if (lane < OUT_DIM / 2) {
        float2 acc2 = make_float2(0.f, 0.f);
        const float2* H2 = (const float2*)g_h2Wt;
#pragma unroll 8
        for (int c = 0; c < HID / 2; ++c) {
            float zv = zsh[w][c];
            float2 wv = H2[c * (OUT_DIM / 2) + lane];
            acc2.x += zv * wv.x;
            acc2.y += zv * wv.y;
        }
        acc2.x += head2_b[2 * lane];
        acc2.y += head2_b[2 * lane + 1];
        *(float2*)(out + (size_t)node * OUT_DIM + 2 * lane) = acc2;
    }
}

// ----------------------------------------------------------------------------
// Launch
// ----------------------------------------------------------------------------
extern "C" void kernel_launch(void* const* d_in, const int* in_sizes, int n_in,
                              void* d_out, int out_size) {
    const float* x       = (const float*)d_in[0];
    const int*   ei      = (const int*)d_in[1];      // int32 [2, E]
    const float* ew      = (const float*)d_in[2];
    const float* lin1_w  = (const float*)d_in[3];
    const float* lin1_b  = (const float*)d_in[4];
    const float* bn1_g   = (const float*)d_in[5];
    const float* bn1_b   = (const float*)d_in[6];
    const float* bn1_m   = (const float*)d_in[7];
    const float* bn1_v   = (const float*)d_in[8];
    const float* lin2_w  = (const float*)d_in[9];
    const float* lin2_b  = (const float*)d_in[10];
    const float* bn2_g   = (const float*)d_in[11];
    const float* bn2_b   = (const float*)d_in[12];
    const float* bn2_m   = (const float*)d_in[13];
    const float* bn2_v   = (const float*)d_in[14];
    const float* att1_w  = (const float*)d_in[15];
    const float* att1_b  = (const float*)d_in[16];
    const float* att2_w  = (const float*)d_in[17];
    const float* att2_b  = (const float*)d_in[18];
    const float* head1_w = (const float*)d_in[19];
    const float* head1_b = (const float*)d_in[20];
    const float* bn3_g   = (const float*)d_in[21];
    const float* bn3_b   = (const float*)d_in[22];
    const float* bn3_m   = (const float*)d_in[23];
    const float* bn3_v   = (const float*)d_in[24];
    const float* head2_w = (const float*)d_in[25];
    const float* head2_b = (const float*)d_in[26];
    float* out = (float*)d_out;

    zero_kernel<<<(NN + 255) / 256, 256>>>();
    prep_kernel<<<(2 * HID * AH + 255) / 256, 256>>>(
        lin1_w, lin1_b, bn1_g, bn1_b, bn1_m, bn1_v,
        lin2_w, lin2_b, bn2_g, bn2_b, bn2_m, bn2_v,
        att1_w, head1_w, head1_b, bn3_g, bn3_b, bn3_m, bn3_v, head2_w);

    count_kernel<<<(EE + 255) / 256, 256>>>(ei, ew);
    scanA_kernel<<<SCAN_NB, SCAN_B>>>();
    scanB_kernel<<<1, SCAN_NB>>>();
    scanC_kernel<<<SCAN_NB, SCAN_B>>>();
    fill_kernel<<<(EE + 255) / 256, 256>>>(ei, ew);

    stem_kernel<<<(NN + 63) / 64, 256>>>(x);

    for (int k = 0; k < KHOP; ++k) {
        propagate_kernel<<<(NN * 32 + 255) / 256, 256>>>(k);
    }

    att_head_kernel<<<(NN + 7) / 8, 256>>>(att1_b, att2_w, att2_b, head2_b, out);
}

// round 10
// speedup vs baseline: 1.3617x; 1.0034x over previous
#include <cuda_runtime.h>
#include <mma.h>
#include <math.h>
#include <stdint.h>

using namespace nvcuda;

#define NN 50000
#define EE 800000
#define IN_DIM 128
#define HID 128
#define OUT_DIM 40
#define KHOP 10
#define AH 64
#define ALPHA 0.1f
#define EPS 1e-5f

#define SCAN_B 256
#define SCAN_NB ((NN + SCAN_B - 1) / SCAN_B)   // 196

// ----------------------------------------------------------------------------
// Static device scratch
// ----------------------------------------------------------------------------
__device__ float g_xs[(KHOP + 1) * (size_t)NN * HID];   // 281.6 MB: h at every hop
__device__ float g_wsum[NN];
__device__ int   g_deg[NN];
__device__ int   g_rowptr[NN + 1];
__device__ int   g_cursor[NN];
__device__ int   g_bsum[SCAN_NB];
__device__ float2 g_edge[EE];                            // {src bits, enorm} CSR by dest

// weights (half for tensor-core stem, native [n][k] layout) + folded BN consts
__device__ __half g_W1h[HID * IN_DIM];   // [n][k]
__device__ __half g_W2h[HID * HID];      // [n][k]
__device__ float g_attWt1[2 * HID * AH]; // [c][o]
__device__ float g_h1Wt[HID * (HID / 2)];// [c][o]  128x64
__device__ float g_h2Wt[(HID / 2) * OUT_DIM]; // [c][o] 64x40
__device__ float g_A1[HID], g_C1[HID], g_A2[HID], g_C2[HID], g_A3[HID / 2], g_C3[HID / 2];

// ----------------------------------------------------------------------------
// Prep (also zeros per-launch accumulators; grid covers NN)
// ----------------------------------------------------------------------------
__global__ void prep_kernel(const float* __restrict__ lin1_w, const float* __restrict__ lin1_b,
                            const float* __restrict__ bn1_g, const float* __restrict__ bn1_b,
                            const float* __restrict__ bn1_m, const float* __restrict__ bn1_v,
                            const float* __restrict__ lin2_w, const float* __restrict__ lin2_b,
                            const float* __restrict__ bn2_g, const float* __restrict__ bn2_b,
                            const float* __restrict__ bn2_m, const float* __restrict__ bn2_v,
                            const float* __restrict__ att1_w,
                            const float* __restrict__ head1_w, const float* __restrict__ head1_b,
                            const float* __restrict__ bn3_g, const float* __restrict__ bn3_b,
                            const float* __restrict__ bn3_m, const float* __restrict__ bn3_v,
                            const float* __restrict__ head2_w) {
    int tid = blockIdx.x * blockDim.x + threadIdx.x;
    if (tid < NN) { g_wsum[tid] = 0.f; g_deg[tid] = 0; g_cursor[tid] = 0; }
    if (tid < IN_DIM * HID) {
        g_W1h[tid] = __float2half(lin1_w[tid]);   // [n][k] native layout
        g_W2h[tid] = __float2half(lin2_w[tid]);
    }
    if (tid < 2 * HID * AH) {
        int c = tid >> 6, o = tid & 63;
        g_attWt1[tid] = att1_w[o * (2 * HID) + c];
    }
    if (tid < HID * (HID / 2)) {
        int c = tid >> 6, o = tid & 63;
        g_h1Wt[tid] = head1_w[o * HID + c];
    }
    if (tid < (HID / 2) * OUT_DIM) {
        int c = tid / OUT_DIM, o = tid % OUT_DIM;
        g_h2Wt[tid] = head2_w[o * (HID / 2) + c];
    }
    if (tid < HID) {
        float a1 = bn1_g[tid] * rsqrtf(bn1_v[tid] + EPS);
        g_A1[tid] = a1;
        g_C1[tid] = lin1_b[tid] * a1 + bn1_b[tid] - bn1_m[tid] * a1;
        float a2 = bn2_g[tid] * rsqrtf(bn2_v[tid] + EPS);
        g_A2[tid] = a2;
        g_C2[tid] = lin2_b[tid] * a2 + bn2_b[tid] - bn2_m[tid] * a2;
    }
    if (tid < HID / 2) {
        float a3 = bn3_g[tid] * rsqrtf(bn3_v[tid] + EPS);
        g_A3[tid] = a3;
        g_C3[tid] = head1_b[tid] * a3 + bn3_b[tid] - bn3_m[tid] * a3;
    }
}

// ----------------------------------------------------------------------------
// Graph preprocessing
// ----------------------------------------------------------------------------
__global__ void count_kernel(const int* __restrict__ ei, const float* __restrict__ ew) {
    int e = blockIdx.x * blockDim.x + threadIdx.x;
    if (e >= EE) return;
    int row = ei[e];
    int col = ei[EE + e];
    atomicAdd(&g_wsum[row], ew[e]);
    atomicAdd(&g_deg[col], 1);
}

__global__ void scanA_kernel() {
    __shared__ int sh[SCAN_B];
    int t = threadIdx.x;
    int i = blockIdx.x * SCAN_B + t;
    int v = (i < NN) ? g_deg[i] : 0;
    sh[t] = v;
    __syncthreads();
#pragma unroll
    for (int off = SCAN_B / 2; off > 0; off >>= 1) {
        if (t < off) sh[t] += sh[t + off];
        __syncthreads();
    }
    if (t == 0) g_bsum[blockIdx.x] = sh[0];
}

// scanC: block computes its own offset (reduce g_bsum prefix), then local scan
__global__ void scanC_kernel() {
    __shared__ int sh[SCAN_B];
    __shared__ int blockOff;
    int t = threadIdx.x;

    int part = 0;
    for (int i = t; i < blockIdx.x; i += SCAN_B) part += g_bsum[i];
    sh[t] = part;
    __syncthreads();
#pragma unroll
    for (int off = SCAN_B / 2; off > 0; off >>= 1) {
        if (t < off) sh[t] += sh[t + off];
        __syncthreads();
    }
    if (t == 0) blockOff = sh[0];
    __syncthreads();

    int i = blockIdx.x * SCAN_B + t;
    int v = (i < NN) ? g_deg[i] : 0;
    sh[t] = v;
    __syncthreads();
#pragma unroll
    for (int off = 1; off < SCAN_B; off <<= 1) {
        int x = (t >= off) ? sh[t - off] : 0;
        __syncthreads();
        sh[t] += x;
        __syncthreads();
    }
    if (i < NN) g_rowptr[i] = sh[t] - v + blockOff;
    if (i == NN - 1) g_rowptr[NN] = EE;
}

__global__ void fill_kernel(const int* __restrict__ ei, const float* __restrict__ ew) {
    int e = blockIdx.x * blockDim.x + threadIdx.x;
    if (e >= EE) return;
    int row = ei[e];
    int col = ei[EE + e];
    float en = ew[e] / fmaxf(g_wsum[row], 1.0f);
    int pos = g_rowptr[col] + atomicAdd(&g_cursor[col], 1);
    g_edge[pos] = make_float2(__int_as_float(row), en);
}

// ----------------------------------------------------------------------------
// Tensor-core fused stem (wmma fp16 x fp16 -> fp32). BM=64 rows/block, 8 warps.
// Phase 1: h1 = relu(bn1(x @ W1^T))  (H1 kept as half in smem, fp32 in regs)
// Phase 2: xs0 = relu(bn2(h1 @ W2^T)) + h1
// Dynamic smem: Ah[64][128]h (16K) | H1h[64][128]h (16K) | Cs[64][132]f (33K)
// ----------------------------------------------------------------------------
#define CS_LD 132
__global__ __launch_bounds__(256) void stem_kernel(const float* __restrict__ X) {
    extern __shared__ char smem[];
    __half (*Ah)[128]  = (__half(*)[128])(smem);
    __half (*H1h)[128] = (__half(*)[128])(smem + 16384);
    float  (*Cs)[CS_LD] = (float(*)[CS_LD])(smem + 32768);

    int tid = threadIdx.x;
    int m0 = blockIdx.x * 64;
    int wid = tid >> 5;
    int rowT = wid >> 1;            // 0..3 (16-row tile)
    int colT0 = (wid & 1) * 4;      // 0 or 4 (each warp: 4 col tiles)

    int r  = tid >> 2;              // 0..63
    int c0 = (tid & 3) * 32;        // elementwise strip
    int gm = m0 + r;

    // load X -> Ah (half), zero-fill out of range
#pragma unroll
    for (int j = 0; j < 32; j += 4) {
        float4 v = make_float4(0.f, 0.f, 0.f, 0.f);
        if (gm < NN) v = *(const float4*)(X + (size_t)gm * 128 + c0 + j);
        Ah[r][c0 + j]     = __float2half(v.x);
        Ah[r][c0 + j + 1] = __float2half(v.y);
        Ah[r][c0 + j + 2] = __float2half(v.z);
        Ah[r][c0 + j + 3] = __float2half(v.w);
    }
    __syncthreads();

    // ---- phase 1 ----
    wmma::fragment<wmma::accumulator, 16, 16, 16, float> cfr[4];
#pragma unroll
    for (int t = 0; t < 4; ++t) wmma::fill_fragment(cfr[t], 0.f);
#pragma unroll
    for (int kk = 0; kk < 8; ++kk) {
        wmma::fragment<wmma::matrix_a, 16, 16, 16, __half, wmma::row_major> afr;
        wmma::load_matrix_sync(afr, &Ah[rowT * 16][kk * 16], 128);
#pragma unroll
        for (int t = 0; t < 4; ++t) {
            wmma::fragment<wmma::matrix_b, 16, 16, 16, __half, wmma::col_major> bfr;
            wmma::load_matrix_sync(bfr, g_W1h + (colT0 + t) * 16 * 128 + kk * 16, 128);
            wmma::mma_sync(cfr[t], afr, bfr, cfr[t]);
        }
    }
#pragma unroll
    for (int t = 0; t < 4; ++t)
        wmma::store_matrix_sync(&Cs[rowT * 16][(colT0 + t) * 16], cfr[t], CS_LD, wmma::mem_row_major);
    __syncthreads();

    // epilogue 1: bn1+relu -> H1h + fp32 regs for residual
    float h1v[32];
#pragma unroll
    for (int j = 0; j < 32; ++j) {
        int n = c0 + j;
        float v = fmaxf(Cs[r][n] * g_A1[n] + g_C1[n], 0.f);
        h1v[j] = v;
        H1h[r][n] = __float2half(v);
    }
    __syncthreads();

    // ---- phase 2 ----
#pragma unroll
    for (int t = 0; t < 4; ++t) wmma::fill_fragment(cfr[t], 0.f);
#pragma unroll
    for (int kk = 0; kk < 8; ++kk) {
        wmma::fragment<wmma::matrix_a, 16, 16, 16, __half, wmma::row_major> afr;
        wmma::load_matrix_sync(afr, &H1h[rowT * 16][kk * 16], 128);
#pragma unroll
        for (int t = 0; t < 4; ++t) {
            wmma::fragment<wmma::matrix_b, 16, 16, 16, __half, wmma::col_major> bfr;
            wmma::load_matrix_sync(bfr, g_W2h + (colT0 + t) * 16 * 128 + kk * 16, 128);
            wmma::mma_sync(cfr[t], afr, bfr, cfr[t]);
        }
    }
#pragma unroll
    for (int t = 0; t < 4; ++t)
        wmma::store_matrix_sync(&Cs[rowT * 16][(colT0 + t) * 16], cfr[t], CS_LD, wmma::mem_row_major);
    __syncthreads();

    // epilogue 2: bn2+relu+residual -> g_xs[0]
    if (gm < NN) {
#pragma unroll
        for (int j = 0; j < 32; ++j) {
            int n = c0 + j;
            float v = fmaxf(Cs[r][n] * g_A2[n] + g_C2[n], 0.f) + h1v[j];
            g_xs[(size_t)gm * 128 + n] = v;
        }
    }
}
#define STEM_SMEM (16384 + 16384 + 64 * CS_LD * 4)

// ----------------------------------------------------------------------------
// Propagation: warp per node, CSR, no atomics, unroll x4, L1-bypass gathers
// ----------------------------------------------------------------------------
__global__ void propagate_kernel(int k) {
    const size_t layer = (size_t)NN * HID;
    const float* __restrict__ hin = g_xs + (size_t)k * layer;
    float* __restrict__ hout = g_xs + (size_t)(k + 1) * layer;

    int gt = blockIdx.x * blockDim.x + threadIdx.x;
    int node = gt >> 5;
    int lane = gt & 31;
    if (node >= NN) return;
    int s = g_rowptr[node];
    int e = g_rowptr[node + 1];
    const float4* __restrict__ hin4 = (const float4*)hin;

    float4 acc0 = make_float4(0.f, 0.f, 0.f, 0.f);
    float4 acc1 = make_float4(0.f, 0.f, 0.f, 0.f);
    float4 acc2 = make_float4(0.f, 0.f, 0.f, 0.f);
    float4 acc3 = make_float4(0.f, 0.f, 0.f, 0.f);

    int deg = e - s;
    int i = s;
    int n4 = s + (deg & ~3);
    for (; i < n4; i += 4) {
        float2 e0 = g_edge[i];
        float2 e1 = g_edge[i + 1];
        float2 e2 = g_edge[i + 2];
        float2 e3 = g_edge[i + 3];
        int s0 = __float_as_int(e0.x);
        int s1 = __float_as_int(e1.x);
        int s2 = __float_as_int(e2.x);
        int s3 = __float_as_int(e3.x);
        float4 v0 = __ldcg(&hin4[(size_t)s0 * 32 + lane]);
        float4 v1 = __ldcg(&hin4[(size_t)s1 * 32 + lane]);
        float4 v2 = __ldcg(&hin4[(size_t)s2 * 32 + lane]);
        float4 v3 = __ldcg(&hin4[(size_t)s3 * 32 + lane]);
        acc0.x += e0.y * v0.x; acc0.y += e0.y * v0.y; acc0.z += e0.y * v0.z; acc0.w += e0.y * v0.w;
        acc1.x += e1.y * v1.x; acc1.y += e1.y * v1.y; acc1.z += e1.y * v1.z; acc1.w += e1.y * v1.w;
        acc2.x += e2.y * v2.x; acc2.y += e2.y * v2.y; acc2.z += e2.y * v2.z; acc2.w += e2.y * v2.w;
        acc3.x += e3.y * v3.x; acc3.y += e3.y * v3.y; acc3.z += e3.y * v3.z; acc3.w += e3.y * v3.w;
    }
    for (; i < e; ++i) {
        float2 e0 = g_edge[i];
        int s0 = __float_as_int(e0.x);
        float4 v0 = __ldcg(&hin4[(size_t)s0 * 32 + lane]);
        acc0.x += e0.y * v0.x; acc0.y += e0.y * v0.y; acc0.z += e0.y * v0.z; acc0.w += e0.y * v0.w;
    }
    float4 b = __ldcg(&((const float4*)g_xs)[(size_t)node * 32 + lane]);
    float4 o;
    o.x = (1.f - ALPHA) * ((acc0.x + acc1.x) + (acc2.x + acc3.x)) + ALPHA * b.x;
    o.y = (1.f - ALPHA) * ((acc0.y + acc1.y) + (acc2.y + acc3.y)) + ALPHA * b.y;
    o.z = (1.f - ALPHA) * ((acc0.z + acc1.z) + (acc2.z + acc3.z)) + ALPHA * b.z;
    o.w = (1.f - ALPHA) * ((acc0.w + acc1.w) + (acc2.w + acc3.w)) + ALPHA * b.w;
    ((float4*)hout)[(size_t)node * 32 + lane] = o;
}

// ----------------------------------------------------------------------------
// Merged attention + hop fusion + head MLP
// ----------------------------------------------------------------------------
__global__ void att_head_kernel(const float* __restrict__ att1_b,
                                const float* __restrict__ att2_w,
                                const float* __restrict__ att2_b,
                                const float* __restrict__ head2_b,
                                float* __restrict__ out) {
    __shared__ float ctx_sh[8][2 * HID];
    __shared__ float a1_sh[8][AH];
    __shared__ float fsh[8][HID];
    __shared__ float zsh[8][HID / 2];
    int w = threadIdx.x >> 5;
    int lane = threadIdx.x & 31;
    int node = blockIdx.x * 8 + w;
    if (node >= NN) return;

    const float4* x0 = (const float4*)g_xs;
    const float4* xK = (const float4*)(g_xs + (size_t)KHOP * NN * HID);
    float4 v0 = x0[(size_t)node * 32 + lane];
    float4 vK = xK[(size_t)node * 32 + lane];
    *(float4*)&ctx_sh[w][lane * 4] = v0;
    *(float4*)&ctx_sh[w][HID + lane * 4] = vK;
    __syncwarp();

    float2 acc = make_float2(0.f, 0.f);
    const float2* W2 = (const float2*)g_attWt1;
#pragma unroll 8
    for (int c = 0; c < 2 * HID; ++c) {
        float xv = ctx_sh[w][c];
        float2 wv = W2[c * (AH / 2) + lane];
        acc.x += xv * wv.x;
        acc.y += xv * wv.y;
    }
    float z0 = acc.x + att1_b[2 * lane];
    float z1 = acc.y + att1_b[2 * lane + 1];
    float g0 = 0.5f * z0 * (1.f + erff(z0 * 0.7071067811865475f));
    float g1 = 0.5f * z1 * (1.f + erff(z1 * 0.7071067811865475f));
    a1_sh[w][2 * lane] = g0;
    a1_sh[w][2 * lane + 1] = g1;
    __syncwarp();

    float logit = -INFINITY;
    if (lane < KHOP + 1) {
        float s = att2_b[lane];
#pragma unroll 8
        for (int c = 0; c < AH; ++c) s += a1_sh[w][c] * att2_w[lane * AH + c];
        logit = s;
    }
    float m = logit;
#pragma unroll
    for (int off = 16; off; off >>= 1) m = fmaxf(m, __shfl_xor_sync(0xffffffffu, m, off));
    float p = (lane < KHOP + 1) ? expf(logit - m) : 0.f;
    float sum = p;
#pragma unroll
    for (int off = 16; off; off >>= 1) sum += __shfl_xor_sync(0xffffffffu, sum, off);
    float prob = p / sum;

    float wk[KHOP + 1];
#pragma unroll
    for (int k = 0; k <= KHOP; ++k) wk[k] = __shfl_sync(0xffffffffu, prob, k);

    float4 f;
    f.x = wk[0] * v0.x + wk[KHOP] * vK.x;
    f.y = wk[0] * v0.y + wk[KHOP] * vK.y;
    f.z = wk[0] * v0.z + wk[KHOP] * vK.z;
    f.w = wk[0] * v0.w + wk[KHOP] * vK.w;
#pragma unroll
    for (int k = 1; k < KHOP; ++k) {
        const float4* xk = (const float4*)(g_xs + (size_t)k * NN * HID);
        float4 v = xk[(size_t)node * 32 + lane];
        f.x += wk[k] * v.x; f.y += wk[k] * v.y; f.z += wk[k] * v.z; f.w += wk[k] * v.w;
    }
    *(float4*)&fsh[w][lane * 4] = f;
    __syncwarp();

    float2 acch = make_float2(0.f, 0.f);
    const float2* H1 = (const float2*)g_h1Wt;
#pragma unroll 8
    for (int c = 0; c < HID; ++c) {
        float xv = fsh[w][c];
        float2 wv = H1[c * (HID / 4) + lane];
        acch.x += xv * wv.x;
        acch.y += xv * wv.y;
    }
    zsh[w][2 * lane]     = fmaxf(acch.x * g_A3[2 * lane] + g_C3[2 * lane], 0.f);
    zsh[w][2 * lane + 1] = fmaxf(acch.y * g_A3[2 * lane + 1] + g_C3[2 * lane + 1], 0.f);
    __syncwarp();

    if (lane < OUT_DIM / 2) {
        float2 acc2 = make_float2(0.f, 0.f);
        const float2* H2 = (const float2*)g_h2Wt;
#pragma unroll 8
        for (int c = 0; c < HID / 2; ++c) {
            float zv = zsh[w][c];
            float2 wv = H2[c * (OUT_DIM / 2) + lane];
            acc2.x += zv * wv.x;
            acc2.y += zv * wv.y;
        }
        acc2.x += head2_b[2 * lane];
        acc2.y += head2_b[2 * lane + 1];
        *(float2*)(out + (size_t)node * OUT_DIM + 2 * lane) = acc2;
    }
}

// ----------------------------------------------------------------------------
// Launch
// ----------------------------------------------------------------------------
extern "C" void kernel_launch(void* const* d_in, const int* in_sizes, int n_in,
                              void* d_out, int out_size) {
    const float* x       = (const float*)d_in[0];
    const int*   ei      = (const int*)d_in[1];      // int32 [2, E]
    const float* ew      = (const float*)d_in[2];
    const float* lin1_w  = (const float*)d_in[3];
    const float* lin1_b  = (const float*)d_in[4];
    const float* bn1_g   = (const float*)d_in[5];
    const float* bn1_b   = (const float*)d_in[6];
    const float* bn1_m   = (const float*)d_in[7];
    const float* bn1_v   = (const float*)d_in[8];
    const float* lin2_w  = (const float*)d_in[9];
    const float* lin2_b  = (const float*)d_in[10];
    const float* bn2_g   = (const float*)d_in[11];
    const float* bn2_b   = (const float*)d_in[12];
    const float* bn2_m   = (const float*)d_in[13];
    const float* bn2_v   = (const float*)d_in[14];
    const float* att1_w  = (const float*)d_in[15];
    const float* att1_b  = (const float*)d_in[16];
    const float* att2_w  = (const float*)d_in[17];
    const float* att2_b  = (const float*)d_in[18];
    const float* head1_w = (const float*)d_in[19];
    const float* head1_b = (const float*)d_in[20];
    const float* bn3_g   = (const float*)d_in[21];
    const float* bn3_b   = (const float*)d_in[22];
    const float* bn3_m   = (const float*)d_in[23];
    const float* bn3_v   = (const float*)d_in[24];
    const float* head2_w = (const float*)d_in[25];
    const float* head2_b = (const float*)d_in[26];
    float* out = (float*)d_out;

    cudaFuncSetAttribute(stem_kernel, cudaFuncAttributeMaxDynamicSharedMemorySize, STEM_SMEM);

    prep_kernel<<<(NN + 255) / 256, 256>>>(
        lin1_w, lin1_b, bn1_g, bn1_b, bn1_m, bn1_v,
        lin2_w, lin2_b, bn2_g, bn2_b, bn2_m, bn2_v,
        att1_w, head1_w, head1_b, bn3_g, bn3_b, bn3_m, bn3_v, head2_w);

    count_kernel<<<(EE + 255) / 256, 256>>>(ei, ew);
    scanA_kernel<<<SCAN_NB, SCAN_B>>>();
    scanC_kernel<<<SCAN_NB, SCAN_B>>>();
    fill_kernel<<<(EE + 255) / 256, 256>>>(ei, ew);

    stem_kernel<<<(NN + 63) / 64, 256, STEM_SMEM>>>(x);

    for (int k = 0; k < KHOP; ++k) {
        propagate_kernel<<<(NN * 32 + 255) / 256, 256>>>(k);
    }

    att_head_kernel<<<(NN + 7) / 8, 256>>>(att1_b, att2_w, att2_b, head2_b, out);
}

// round 11
// speedup vs baseline: 1.6905x; 1.2414x over previous
#include <cuda_runtime.h>
#include <mma.h>
#include <math.h>
#include <stdint.h>

using namespace nvcuda;

#define NN 50000
#define EE 800000
#define IN_DIM 128
#define HID 128
#define OUT_DIM 40
#define KHOP 10
#define AH 64
#define ALPHA 0.1f
#define EPS 1e-5f

#define SCAN_B 256
#define SCAN_NB ((NN + SCAN_B - 1) / SCAN_B)   // 196

// ----------------------------------------------------------------------------
// Static device scratch
// ----------------------------------------------------------------------------
__device__ float g_xs[(KHOP + 1) * (size_t)NN * HID];   // 281.6 MB: h at every hop
__device__ float g_wsum[NN];
__device__ int   g_deg[NN];
__device__ int   g_rowptr[NN + 1];
__device__ int   g_cursor[NN];
__device__ int   g_bsum[SCAN_NB];
__device__ float2 g_edge[EE];                            // {src bits, enorm} CSR by dest

// half weights (native [o][c] layouts -> col_major wmma B, no transpose needed)
__device__ __half g_W1h[HID * IN_DIM];        // [n][k]
__device__ __half g_W2h[HID * HID];           // [n][k]
__device__ __half g_attW1h[AH * 2 * HID];     // [o][c]  64 x 256
__device__ __half g_attW2h[16 * AH];          // [j][c]  16 x 64 (rows 11..15 = 0)
__device__ __half g_h1Wh[(HID / 2) * HID];    // [o][c]  64 x 128
__device__ __half g_h2Wh[48 * (HID / 2)];     // [j][c]  48 x 64 (rows 40..47 = 0)
__device__ float g_A1[HID], g_C1[HID], g_A2[HID], g_C2[HID], g_A3[HID / 2], g_C3[HID / 2];

// ----------------------------------------------------------------------------
// Prep (also zeros per-launch accumulators; grid covers NN)
// ----------------------------------------------------------------------------
__global__ void prep_kernel(const float* __restrict__ lin1_w, const float* __restrict__ lin1_b,
                            const float* __restrict__ bn1_g, const float* __restrict__ bn1_b,
                            const float* __restrict__ bn1_m, const float* __restrict__ bn1_v,
                            const float* __restrict__ lin2_w, const float* __restrict__ lin2_b,
                            const float* __restrict__ bn2_g, const float* __restrict__ bn2_b,
                            const float* __restrict__ bn2_m, const float* __restrict__ bn2_v,
                            const float* __restrict__ att1_w,
                            const float* __restrict__ head1_w, const float* __restrict__ head1_b,
                            const float* __restrict__ bn3_g, const float* __restrict__ bn3_b,
                            const float* __restrict__ bn3_m, const float* __restrict__ bn3_v,
                            const float* __restrict__ head2_w) {
    int tid = blockIdx.x * blockDim.x + threadIdx.x;
    if (tid < NN) { g_wsum[tid] = 0.f; g_deg[tid] = 0; g_cursor[tid] = 0; }
    if (tid < IN_DIM * HID) {
        g_W1h[tid] = __float2half(lin1_w[tid]);   // [n][k] native
        g_W2h[tid] = __float2half(lin2_w[tid]);
    }
    if (tid < AH * 2 * HID) g_attW1h[tid] = __float2half(att1_w[tid]);   // [o][c] native
    if (tid < 16 * AH) {
        int j = tid >> 6, c = tid & 63;
        g_attW2h[tid] = __float2half(j < KHOP + 1 ? /*att2_w*/ 0.f : 0.f);  // filled below w/ arg
    }
    if (tid < (HID / 2) * HID) g_h1Wh[tid] = __float2half(head1_w[tid]); // [o][c] native
    if (tid < 48 * (HID / 2)) {
        int j = tid / 64;
        g_h2Wh[tid] = __float2half(j < OUT_DIM ? head2_w[tid - (tid / 64 - j) /*== j*64+c*/] : 0.f);
    }
    if (tid < HID) {
        float a1 = bn1_g[tid] * rsqrtf(bn1_v[tid] + EPS);
        g_A1[tid] = a1;
        g_C1[tid] = lin1_b[tid] * a1 + bn1_b[tid] - bn1_m[tid] * a1;
        float a2 = bn2_g[tid] * rsqrtf(bn2_v[tid] + EPS);
        g_A2[tid] = a2;
        g_C2[tid] = lin2_b[tid] * a2 + bn2_b[tid] - bn2_m[tid] * a2;
    }
    if (tid < HID / 2) {
        float a3 = bn3_g[tid] * rsqrtf(bn3_v[tid] + EPS);
        g_A3[tid] = a3;
        g_C3[tid] = head1_b[tid] * a3 + bn3_b[tid] - bn3_m[tid] * a3;
    }
}

// att2 weights need their own tiny copy kernel (clean indexing, padded rows zero)
__global__ void prep_att2_kernel(const float* __restrict__ att2_w) {
    int tid = blockIdx.x * blockDim.x + threadIdx.x;   // 16*64 = 1024 threads
    if (tid < 16 * AH) {
        int j = tid >> 6, c = tid & 63;
        g_attW2h[tid] = __float2half(j < KHOP + 1 ? att2_w[j * AH + c] : 0.f);
    }
}

// ----------------------------------------------------------------------------
// Graph preprocessing
// ----------------------------------------------------------------------------
__global__ void count_kernel(const int* __restrict__ ei, const float* __restrict__ ew) {
    int e = blockIdx.x * blockDim.x + threadIdx.x;
    if (e >= EE) return;
    int row = ei[e];
    int col = ei[EE + e];
    atomicAdd(&g_wsum[row], ew[e]);
    atomicAdd(&g_deg[col], 1);
}

__global__ void scanA_kernel() {
    __shared__ int sh[SCAN_B];
    int t = threadIdx.x;
    int i = blockIdx.x * SCAN_B + t;
    int v = (i < NN) ? g_deg[i] : 0;
    sh[t] = v;
    __syncthreads();
#pragma unroll
    for (int off = SCAN_B / 2; off > 0; off >>= 1) {
        if (t < off) sh[t] += sh[t + off];
        __syncthreads();
    }
    if (t == 0) g_bsum[blockIdx.x] = sh[0];
}

__global__ void scanC_kernel() {
    __shared__ int sh[SCAN_B];
    __shared__ int blockOff;
    int t = threadIdx.x;

    int part = 0;
    for (int i = t; i < blockIdx.x; i += SCAN_B) part += g_bsum[i];
    sh[t] = part;
    __syncthreads();
#pragma unroll
    for (int off = SCAN_B / 2; off > 0; off >>= 1) {
        if (t < off) sh[t] += sh[t + off];
        __syncthreads();
    }
    if (t == 0) blockOff = sh[0];
    __syncthreads();

    int i = blockIdx.x * SCAN_B + t;
    int v = (i < NN) ? g_deg[i] : 0;
    sh[t] = v;
    __syncthreads();
#pragma unroll
    for (int off = 1; off < SCAN_B; off <<= 1) {
        int x = (t >= off) ? sh[t - off] : 0;
        __syncthreads();
        sh[t] += x;
        __syncthreads();
    }
    if (i < NN) g_rowptr[i] = sh[t] - v + blockOff;
    if (i == NN - 1) g_rowptr[NN] = EE;
}

__global__ void fill_kernel(const int* __restrict__ ei, const float* __restrict__ ew) {
    int e = blockIdx.x * blockDim.x + threadIdx.x;
    if (e >= EE) return;
    int row = ei[e];
    int col = ei[EE + e];
    float en = ew[e] / fmaxf(g_wsum[row], 1.0f);
    int pos = g_rowptr[col] + atomicAdd(&g_cursor[col], 1);
    g_edge[pos] = make_float2(__int_as_float(row), en);
}

// ----------------------------------------------------------------------------
// Tensor-core fused stem (unchanged from R10)
// ----------------------------------------------------------------------------
#define CS_LD 132
__global__ __launch_bounds__(256) void stem_kernel(const float* __restrict__ X) {
    extern __shared__ char smem[];
    __half (*Ah)[128]  = (__half(*)[128])(smem);
    __half (*H1h)[128] = (__half(*)[128])(smem + 16384);
    float  (*Cs)[CS_LD] = (float(*)[CS_LD])(smem + 32768);

    int tid = threadIdx.x;
    int m0 = blockIdx.x * 64;
    int wid = tid >> 5;
    int rowT = wid >> 1;
    int colT0 = (wid & 1) * 4;

    int r  = tid >> 2;
    int c0 = (tid & 3) * 32;
    int gm = m0 + r;

#pragma unroll
    for (int j = 0; j < 32; j += 4) {
        float4 v = make_float4(0.f, 0.f, 0.f, 0.f);
        if (gm < NN) v = *(const float4*)(X + (size_t)gm * 128 + c0 + j);
        Ah[r][c0 + j]     = __float2half(v.x);
        Ah[r][c0 + j + 1] = __float2half(v.y);
        Ah[r][c0 + j + 2] = __float2half(v.z);
        Ah[r][c0 + j + 3] = __float2half(v.w);
    }
    __syncthreads();

    wmma::fragment<wmma::accumulator, 16, 16, 16, float> cfr[4];
#pragma unroll
    for (int t = 0; t < 4; ++t) wmma::fill_fragment(cfr[t], 0.f);
#pragma unroll
    for (int kk = 0; kk < 8; ++kk) {
        wmma::fragment<wmma::matrix_a, 16, 16, 16, __half, wmma::row_major> afr;
        wmma::load_matrix_sync(afr, &Ah[rowT * 16][kk * 16], 128);
#pragma unroll
        for (int t = 0; t < 4; ++t) {
            wmma::fragment<wmma::matrix_b, 16, 16, 16, __half, wmma::col_major> bfr;
            wmma::load_matrix_sync(bfr, g_W1h + (colT0 + t) * 16 * 128 + kk * 16, 128);
            wmma::mma_sync(cfr[t], afr, bfr, cfr[t]);
        }
    }
#pragma unroll
    for (int t = 0; t < 4; ++t)
        wmma::store_matrix_sync(&Cs[rowT * 16][(colT0 + t) * 16], cfr[t], CS_LD, wmma::mem_row_major);
    __syncthreads();

    float h1v[32];
#pragma unroll
    for (int j = 0; j < 32; ++j) {
        int n = c0 + j;
        float v = fmaxf(Cs[r][n] * g_A1[n] + g_C1[n], 0.f);
        h1v[j] = v;
        H1h[r][n] = __float2half(v);
    }
    __syncthreads();

#pragma unroll
    for (int t = 0; t < 4; ++t) wmma::fill_fragment(cfr[t], 0.f);
#pragma unroll
    for (int kk = 0; kk < 8; ++kk) {
        wmma::fragment<wmma::matrix_a, 16, 16, 16, __half, wmma::row_major> afr;
        wmma::load_matrix_sync(afr, &H1h[rowT * 16][kk * 16], 128);
#pragma unroll
        for (int t = 0; t < 4; ++t) {
            wmma::fragment<wmma::matrix_b, 16, 16, 16, __half, wmma::col_major> bfr;
            wmma::load_matrix_sync(bfr, g_W2h + (colT0 + t) * 16 * 128 + kk * 16, 128);
            wmma::mma_sync(cfr[t], afr, bfr, cfr[t]);
        }
    }
#pragma unroll
    for (int t = 0; t < 4; ++t)
        wmma::store_matrix_sync(&Cs[rowT * 16][(colT0 + t) * 16], cfr[t], CS_LD, wmma::mem_row_major);
    __syncthreads();

    if (gm < NN) {
#pragma unroll
        for (int j = 0; j < 32; ++j) {
            int n = c0 + j;
            float v = fmaxf(Cs[r][n] * g_A2[n] + g_C2[n], 0.f) + h1v[j];
            g_xs[(size_t)gm * 128 + n] = v;
        }
    }
}
#define STEM_SMEM (16384 + 16384 + 64 * CS_LD * 4)

// ----------------------------------------------------------------------------
// Propagation (unchanged from R9/R10)
// ----------------------------------------------------------------------------
__global__ void propagate_kernel(int k) {
    const size_t layer = (size_t)NN * HID;
    const float* __restrict__ hin = g_xs + (size_t)k * layer;
    float* __restrict__ hout = g_xs + (size_t)(k + 1) * layer;

    int gt = blockIdx.x * blockDim.x + threadIdx.x;
    int node = gt >> 5;
    int lane = gt & 31;
    if (node >= NN) return;
    int s = g_rowptr[node];
    int e = g_rowptr[node + 1];
    const float4* __restrict__ hin4 = (const float4*)hin;

    float4 acc0 = make_float4(0.f, 0.f, 0.f, 0.f);
    float4 acc1 = make_float4(0.f, 0.f, 0.f, 0.f);
    float4 acc2 = make_float4(0.f, 0.f, 0.f, 0.f);
    float4 acc3 = make_float4(0.f, 0.f, 0.f, 0.f);

    int deg = e - s;
    int i = s;
    int n4 = s + (deg & ~3);
    for (; i < n4; i += 4) {
        float2 e0 = g_edge[i];
        float2 e1 = g_edge[i + 1];
        float2 e2 = g_edge[i + 2];
        float2 e3 = g_edge[i + 3];
        int s0 = __float_as_int(e0.x);
        int s1 = __float_as_int(e1.x);
        int s2 = __float_as_int(e2.x);
        int s3 = __float_as_int(e3.x);
        float4 v0 = __ldcg(&hin4[(size_t)s0 * 32 + lane]);
        float4 v1 = __ldcg(&hin4[(size_t)s1 * 32 + lane]);
        float4 v2 = __ldcg(&hin4[(size_t)s2 * 32 + lane]);
        float4 v3 = __ldcg(&hin4[(size_t)s3 * 32 + lane]);
        acc0.x += e0.y * v0.x; acc0.y += e0.y * v0.y; acc0.z += e0.y * v0.z; acc0.w += e0.y * v0.w;
        acc1.x += e1.y * v1.x; acc1.y += e1.y * v1.y; acc1.z += e1.y * v1.z; acc1.w += e1.y * v1.w;
        acc2.x += e2.y * v2.x; acc2.y += e2.y * v2.y; acc2.z += e2.y * v2.z; acc2.w += e2.y * v2.w;
        acc3.x += e3.y * v3.x; acc3.y += e3.y * v3.y; acc3.z += e3.y * v3.z; acc3.w += e3.y * v3.w;
    }
    for (; i < e; ++i) {
        float2 e0 = g_edge[i];
        int s0 = __float_as_int(e0.x);
        float4 v0 = __ldcg(&hin4[(size_t)s0 * 32 + lane]);
        acc0.x += e0.y * v0.x; acc0.y += e0.y * v0.y; acc0.z += e0.y * v0.z; acc0.w += e0.y * v0.w;
    }
    float4 b = __ldcg(&((const float4*)g_xs)[(size_t)node * 32 + lane]);
    float4 o;
    o.x = (1.f - ALPHA) * ((acc0.x + acc1.x) + (acc2.x + acc3.x)) + ALPHA * b.x;
    o.y = (1.f - ALPHA) * ((acc0.y + acc1.y) + (acc2.y + acc3.y)) + ALPHA * b.y;
    o.z = (1.f - ALPHA) * ((acc0.z + acc1.z) + (acc2.z + acc3.z)) + ALPHA * b.z;
    o.w = (1.f - ALPHA) * ((acc0.w + acc1.w) + (acc2.w + acc3.w)) + ALPHA * b.w;
    ((float4*)hout)[(size_t)node * 32 + lane] = o;
}

// ----------------------------------------------------------------------------
// wmma attention + hop fusion + head. 64 nodes/block, 256 threads (8 warps).
// Dynamic smem layout (bytes):
//   CTXh [64][256]h : 0      (32768)
//   A1h  [64][64]h  : 32768  (8192)
//   FUSh [64][128]h : 40960  (16384)
//   Zh   [64][64]h  : 57344  (8192)
//   Cs   [64][68]f  : 65536  (17408)
//   WK   [64][16]f  : 82944  (4096)
// ----------------------------------------------------------------------------
#define ATT_CS_LD 68
#define ATT_SMEM (32768 + 8192 + 16384 + 8192 + 64 * ATT_CS_LD * 4 + 4096)
__global__ __launch_bounds__(256) void att_head_kernel(const float* __restrict__ att1_b,
                                                       const float* __restrict__ att2_b,
                                                       const float* __restrict__ head2_b,
                                                       float* __restrict__ out) {
    extern __shared__ char sm[];
    __half (*CTXh)[256] = (__half(*)[256])(sm);
    __half (*A1h)[64]   = (__half(*)[64])(sm + 32768);
    __half (*FUSh)[128] = (__half(*)[128])(sm + 40960);
    __half (*Zh)[64]    = (__half(*)[64])(sm + 57344);
    float  (*Cs)[ATT_CS_LD] = (float(*)[ATT_CS_LD])(sm + 65536);
    float  (*WK)[16]    = (float(*)[16])(sm + 82944);

    const size_t layer = (size_t)NN * HID;
    int tid = threadIdx.x;
    int wid = tid >> 5;
    int m0 = blockIdx.x * 64;
    int r  = tid >> 2;              // 0..63
    int c0 = (tid & 3) * 32;        // feature strip
    int gm = m0 + r;

    // warp tile mapping for 4x4-tile GEMMs: two row-tiles, one col-tile per warp
    int tr0 = wid >> 2;             // 0..1
    int tr1 = tr0 + 2;              // 2..3
    int tcw = wid & 3;              // 0..3

    // ---- load ctx = [x0 | xK] as half ----
    {
        const float* x0 = g_xs;
        const float* xK = g_xs + (size_t)KHOP * layer;
#pragma unroll
        for (int j = 0; j < 32; j += 4) {
            float4 v = make_float4(0.f, 0.f, 0.f, 0.f);
            float4 u = make_float4(0.f, 0.f, 0.f, 0.f);
            if (gm < NN) {
                v = *(const float4*)(x0 + (size_t)gm * 128 + c0 + j);
                u = *(const float4*)(xK + (size_t)gm * 128 + c0 + j);
            }
            CTXh[r][c0 + j]     = __float2half(v.x);
            CTXh[r][c0 + j + 1] = __float2half(v.y);
            CTXh[r][c0 + j + 2] = __float2half(v.z);
            CTXh[r][c0 + j + 3] = __float2half(v.w);
            CTXh[r][128 + c0 + j]     = __float2half(u.x);
            CTXh[r][128 + c0 + j + 1] = __float2half(u.y);
            CTXh[r][128 + c0 + j + 2] = __float2half(u.z);
            CTXh[r][128 + c0 + j + 3] = __float2half(u.w);
        }
    }
    __syncthreads();

    // ---- att1: ctx(64x256) @ att1W^T -> Cs(64x64) ----
    {
        wmma::fragment<wmma::accumulator, 16, 16, 16, float> acc0, acc1;
        wmma::fill_fragment(acc0, 0.f);
        wmma::fill_fragment(acc1, 0.f);
#pragma unroll
        for (int kk = 0; kk < 16; ++kk) {
            wmma::fragment<wmma::matrix_b, 16, 16, 16, __half, wmma::col_major> bfr;
            wmma::load_matrix_sync(bfr, g_attW1h + tcw * 16 * 256 + kk * 16, 256);
            wmma::fragment<wmma::matrix_a, 16, 16, 16, __half, wmma::row_major> afr;
            wmma::load_matrix_sync(afr, &CTXh[tr0 * 16][kk * 16], 256);
            wmma::mma_sync(acc0, afr, bfr, acc0);
            wmma::load_matrix_sync(afr, &CTXh[tr1 * 16][kk * 16], 256);
            wmma::mma_sync(acc1, afr, bfr, acc1);
        }
        wmma::store_matrix_sync(&Cs[tr0 * 16][tcw * 16], acc0, ATT_CS_LD, wmma::mem_row_major);
        wmma::store_matrix_sync(&Cs[tr1 * 16][tcw * 16], acc1, ATT_CS_LD, wmma::mem_row_major);
    }
    __syncthreads();

    // ---- bias + exact gelu -> A1h ----
    {
        int cc = (tid & 3) * 16;
#pragma unroll
        for (int j = 0; j < 16; ++j) {
            int n = cc + j;
            float z = Cs[r][n] + att1_b[n];
            float g = 0.5f * z * (1.f + erff(z * 0.7071067811865475f));
            A1h[r][n] = __float2half(g);
        }
    }
    __syncthreads();

    // ---- att2: A1(64x64) @ att2W^T -> Cs(64x16) ----
    if (wid < 4) {
        wmma::fragment<wmma::accumulator, 16, 16, 16, float> acc;
        wmma::fill_fragment(acc, 0.f);
#pragma unroll
        for (int kk = 0; kk < 4; ++kk) {
            wmma::fragment<wmma::matrix_a, 16, 16, 16, __half, wmma::row_major> afr;
            wmma::fragment<wmma::matrix_b, 16, 16, 16, __half, wmma::col_major> bfr;
            wmma::load_matrix_sync(afr, &A1h[wid * 16][kk * 16], 64);
            wmma::load_matrix_sync(bfr, g_attW2h + kk * 16, 64);
            wmma::mma_sync(acc, afr, bfr, acc);
        }
        wmma::store_matrix_sync(&Cs[wid * 16][0], acc, ATT_CS_LD, wmma::mem_row_major);
    }
    __syncthreads();

    // ---- softmax over K+1=11 logits per node ----
    if (tid < 64) {
        float lg[KHOP + 1];
        float m = -INFINITY;
#pragma unroll
        for (int j = 0; j <= KHOP; ++j) {
            lg[j] = Cs[tid][j] + att2_b[j];
            m = fmaxf(m, lg[j]);
        }
        float sum = 0.f;
#pragma unroll
        for (int j = 0; j <= KHOP; ++j) { lg[j] = expf(lg[j] - m); sum += lg[j]; }
        float inv = 1.f / sum;
#pragma unroll
        for (int j = 0; j <= KHOP; ++j) WK[tid][j] = lg[j] * inv;
    }
    __syncthreads();

    // ---- hop fusion: fused = sum_k wk * xs[k]  (fp32 accumulate) ----
    {
        float f[32];
#pragma unroll
        for (int j = 0; j < 32; ++j) f[j] = 0.f;
        if (gm < NN) {
#pragma unroll
            for (int k = 0; k <= KHOP; ++k) {
                float wkv = WK[r][k];
                const float4* src = (const float4*)(g_xs + (size_t)k * layer + (size_t)gm * 128 + c0);
#pragma unroll
                for (int j = 0; j < 8; ++j) {
                    float4 v = __ldcg(&src[j]);
                    f[j * 4]     += wkv * v.x;
                    f[j * 4 + 1] += wkv * v.y;
                    f[j * 4 + 2] += wkv * v.z;
                    f[j * 4 + 3] += wkv * v.w;
                }
            }
        }
#pragma unroll
        for (int j = 0; j < 32; ++j) FUSh[r][c0 + j] = __float2half(f[j]);
    }
    __syncthreads();

    // ---- head1: fused(64x128) @ head1W^T -> Cs(64x64) ----
    {
        wmma::fragment<wmma::accumulator, 16, 16, 16, float> acc0, acc1;
        wmma::fill_fragment(acc0, 0.f);
        wmma::fill_fragment(acc1, 0.f);
#pragma unroll
        for (int kk = 0; kk < 8; ++kk) {
            wmma::fragment<wmma::matrix_b, 16, 16, 16, __half, wmma::col_major> bfr;
            wmma::load_matrix_sync(bfr, g_h1Wh + tcw * 16 * 128 + kk * 16, 128);
            wmma::fragment<wmma::matrix_a, 16, 16, 16, __half, wmma::row_major> afr;
            wmma::load_matrix_sync(afr, &FUSh[tr0 * 16][kk * 16], 128);
            wmma::mma_sync(acc0, afr, bfr, acc0);
            wmma::load_matrix_sync(afr, &FUSh[tr1 * 16][kk * 16], 128);
            wmma::mma_sync(acc1, afr, bfr, acc1);
        }
        wmma::store_matrix_sync(&Cs[tr0 * 16][tcw * 16], acc0, ATT_CS_LD, wmma::mem_row_major);
        wmma::store_matrix_sync(&Cs[tr1 * 16][tcw * 16], acc1, ATT_CS_LD, wmma::mem_row_major);
    }
    __syncthreads();

    // ---- bn3 + relu -> Zh ----
    {
        int cc = (tid & 3) * 16;
#pragma unroll
        for (int j = 0; j < 16; ++j) {
            int n = cc + j;
            float v = fmaxf(Cs[r][n] * g_A3[n] + g_C3[n], 0.f);
            Zh[r][n] = __float2half(v);
        }
    }
    __syncthreads();

    // ---- head2: z(64x64) @ head2W^T -> Cs(64x48) ----
    {
        for (int t = wid; t < 12; t += 8) {
            int tr = t / 3, tc = t % 3;
            wmma::fragment<wmma::accumulator, 16, 16, 16, float> acc;
            wmma::fill_fragment(acc, 0.f);
#pragma unroll
            for (int kk = 0; kk < 4; ++kk) {
                wmma::fragment<wmma::matrix_a, 16, 16, 16, __half, wmma::row_major> afr;
                wmma::fragment<wmma::matrix_b, 16, 16, 16, __half, wmma::col_major> bfr;
                wmma::load_matrix_sync(afr, &Zh[tr * 16][kk * 16], 64);
                wmma::load_matrix_sync(bfr, g_h2Wh + tc * 16 * 64 + kk * 16, 64);
                wmma::mma_sync(acc, afr, bfr, acc);
            }
            wmma::store_matrix_sync(&Cs[tr * 16][tc * 16], acc, ATT_CS_LD, wmma::mem_row_major);
        }
    }
    __syncthreads();

    // ---- biased write of 64x40 output tile ----
    for (int p = tid; p < 64 * OUT_DIM; p += 256) {
        int row = p / OUT_DIM, col = p % OUT_DIM;
        int node = m0 + row;
        if (node < NN) out[(size_t)node * OUT_DIM + col] = Cs[row][col] + head2_b[col];
    }
}

// ----------------------------------------------------------------------------
// Launch
// ----------------------------------------------------------------------------
extern "C" void kernel_launch(void* const* d_in, const int* in_sizes, int n_in,
                              void* d_out, int out_size) {
    const float* x       = (const float*)d_in[0];
    const int*   ei      = (const int*)d_in[1];      // int32 [2, E]
    const float* ew      = (const float*)d_in[2];
    const float* lin1_w  = (const float*)d_in[3];
    const float* lin1_b  = (const float*)d_in[4];
    const float* bn1_g   = (const float*)d_in[5];
    const float* bn1_b   = (const float*)d_in[6];
    const float* bn1_m   = (const float*)d_in[7];
    const float* bn1_v   = (const float*)d_in[8];
    const float* lin2_w  = (const float*)d_in[9];
    const float* lin2_b  = (const float*)d_in[10];
    const float* bn2_g   = (const float*)d_in[11];
    const float* bn2_b   = (const float*)d_in[12];
    const float* bn2_m   = (const float*)d_in[13];
    const float* bn2_v   = (const float*)d_in[14];
    const float* att1_w  = (const float*)d_in[15];
    const float* att1_b  = (const float*)d_in[16];
    const float* att2_w  = (const float*)d_in[17];
    const float* att2_b  = (const float*)d_in[18];
    const float* head1_w = (const float*)d_in[19];
    const float* head1_b = (const float*)d_in[20];
    const float* bn3_g   = (const float*)d_in[21];
    const float* bn3_b   = (const float*)d_in[22];
    const float* bn3_m   = (const float*)d_in[23];
    const float* bn3_v   = (const float*)d_in[24];
    const float* head2_w = (const float*)d_in[25];
    const float* head2_b = (const float*)d_in[26];
    float* out = (float*)d_out;

    cudaFuncSetAttribute(stem_kernel, cudaFuncAttributeMaxDynamicSharedMemorySize, STEM_SMEM);
    cudaFuncSetAttribute(att_head_kernel, cudaFuncAttributeMaxDynamicSharedMemorySize, ATT_SMEM);

    prep_kernel<<<(NN + 255) / 256, 256>>>(
        lin1_w, lin1_b, bn1_g, bn1_b, bn1_m, bn1_v,
        lin2_w, lin2_b, bn2_g, bn2_b, bn2_m, bn2_v,
        att1_w, head1_w, head1_b, bn3_g, bn3_b, bn3_m, bn3_v, head2_w);
    prep_att2_kernel<<<4, 256>>>(att2_w);

    count_kernel<<<(EE + 255) / 256, 256>>>(ei, ew);
    scanA_kernel<<<SCAN_NB, SCAN_B>>>();
    scanC_kernel<<<SCAN_NB, SCAN_B>>>();
    fill_kernel<<<(EE + 255) / 256, 256>>>(ei, ew);

    stem_kernel<<<(NN + 63) / 64, 256, STEM_SMEM>>>(x);

    for (int k = 0; k < KHOP; ++k) {
        propagate_kernel<<<(NN * 32 + 255) / 256, 256>>>(k);
    }

    att_head_kernel<<<(NN + 63) / 64, 256, ATT_SMEM>>>(att1_b, att2_b, head2_b, out);
}